// round 3
// baseline (speedup 1.0000x reference)
#include <cuda_runtime.h>

// MultiHeadAttention: b=4, n=2048, emb=768, heads=12, head_dim=64, fp32.
// Pipeline: QKV GEMM (scatter to [b,h,n,d]) -> flash attention -> proj GEMM.

#define EMB    768
#define QKV3   2304
#define NHEAD  12
#define HDIM   64
#define BATCH  4
#define SEQ    2048
#define BHT    (BATCH*NHEAD)
#define ATT_SCALE 0.03608439182435161f   // 1/sqrt(768)

// Scratch (allocation-free rule: __device__ globals). 25.2 MB each.
__device__ float g_Q[BHT * SEQ * HDIM];
__device__ float g_K[BHT * SEQ * HDIM];
__device__ float g_V[BHT * SEQ * HDIM];
__device__ float g_O[BHT * SEQ * HDIM];

// ---------------------------------------------------------------------------
// Kernel 1: qkv = x @ W_qkv + b_qkv, scattered into g_Q/g_K/g_V as [b,h,n,d].
// Tiles: BM=BN=64, BK=16. 256 threads, each computes a 4x4 micro-tile.
// ---------------------------------------------------------------------------
__global__ __launch_bounds__(256) void qkv_gemm_kernel(
    const float* __restrict__ x,      // [8192, 768]
    const float* __restrict__ W,      // [768, 2304]
    const float* __restrict__ bias)   // [2304]
{
    __shared__ float Ast[16 * 68];    // A^T tile: [k][m], padded stride 68
    __shared__ float Bs[16 * 64];     // B tile:   [k][n]

    const int t  = threadIdx.x;
    const int tx = t & 15;
    const int ty = t >> 4;
    const int m0 = blockIdx.y * 64;
    const int n0 = blockIdx.x * 64;

    float acc[4][4] = {};

    for (int kb = 0; kb < EMB; kb += 16) {
        #pragma unroll
        for (int l = 0; l < 4; l++) {
            int idx = t + l * 256;                  // 0..1023
            int row = idx >> 4, k = idx & 15;
            Ast[k * 68 + row] = x[(size_t)(m0 + row) * EMB + kb + k];
        }
        #pragma unroll
        for (int l = 0; l < 4; l++) {
            int idx = t + l * 256;
            int k = idx >> 6, n = idx & 63;
            Bs[k * 64 + n] = W[(size_t)(kb + k) * QKV3 + n0 + n];
        }
        __syncthreads();
        #pragma unroll
        for (int k = 0; k < 16; k++) {
            float4 a = *(const float4*)(Ast + k * 68 + ty * 4);
            float4 b = *(const float4*)(Bs  + k * 64 + tx * 4);
            float av[4] = {a.x, a.y, a.z, a.w};
            float bv[4] = {b.x, b.y, b.z, b.w};
            #pragma unroll
            for (int ii = 0; ii < 4; ii++)
                #pragma unroll
                for (int jj = 0; jj < 4; jj++)
                    acc[ii][jj] += av[ii] * bv[jj];
        }
        __syncthreads();
    }

    // Scatter: column j -> h = j/192, d = (j%192)/3, s = j%3 (qkv innermost).
    #pragma unroll
    for (int ii = 0; ii < 4; ii++) {
        int m  = m0 + ty * 4 + ii;
        int bi = m >> 11;           // /2048
        int ni = m & 2047;
        #pragma unroll
        for (int jj = 0; jj < 4; jj++) {
            int col = n0 + tx * 4 + jj;
            int h   = col / 192;
            int rem = col - h * 192;
            int d   = rem / 3;
            int s   = rem - d * 3;
            float v = acc[ii][jj] + bias[col];
            size_t dst = ((size_t)(bi * NHEAD + h) * SEQ + ni) * HDIM + d;
            if (s == 0)      g_Q[dst] = v;
            else if (s == 1) g_K[dst] = v;
            else             g_V[dst] = v;
        }
    }
}

// ---------------------------------------------------------------------------
// Kernel 2: flash attention. One block = 64 query rows of one (b,h).
// Streams over 32 key tiles of 64. Online softmax, fp32.
// Dynamic smem: Qt[64][68] + Kt[64][68] + Pt[64][68] + Vs[64][64] = 68608 B.
// ---------------------------------------------------------------------------
__global__ __launch_bounds__(256) void flash_attn_kernel()
{
    extern __shared__ float sh[];
    float* Qt = sh;                 // [d][i], stride 68
    float* Kt = Qt + 64 * 68;       // [d][j], stride 68
    float* Pt = Kt + 64 * 68;       // [j][i], stride 68
    float* Vs = Pt + 64 * 68;       // [j][d], stride 64

    const int t  = threadIdx.x;
    const int tx = t & 15;
    const int ty = t >> 4;
    const int bh = blockIdx.y;
    const int q0 = blockIdx.x * 64;

    const float* Qg = g_Q + (size_t)bh * SEQ * HDIM;
    const float* Kg = g_K + (size_t)bh * SEQ * HDIM;
    const float* Vg = g_V + (size_t)bh * SEQ * HDIM;
    float*       Og = g_O + (size_t)bh * SEQ * HDIM;

    // Load Q tile transposed (coalesced global read).
    #pragma unroll
    for (int l = 0; l < 16; l++) {
        int idx = t + l * 256;              // 0..4095
        int i = idx >> 6, d = idx & 63;
        Qt[d * 68 + i] = Qg[(size_t)q0 * HDIM + idx];
    }

    float mrow[4] = {-1e30f, -1e30f, -1e30f, -1e30f};
    float lrow[4] = {0.f, 0.f, 0.f, 0.f};
    float o[4][4] = {};

    for (int kt = 0; kt < SEQ / 64; kt++) {
        const int k0 = kt * 64;
        __syncthreads();   // previous iteration's PV reads done
        #pragma unroll
        for (int l = 0; l < 16; l++) {
            int idx = t + l * 256;
            int j = idx >> 6, d = idx & 63;
            float kv = Kg[(size_t)k0 * HDIM + idx];
            Kt[d * 68 + j] = kv;
            Vs[idx]        = Vg[(size_t)k0 * HDIM + idx];
        }
        __syncthreads();

        // S = Q @ K^T (4x4 micro-tile per thread)
        float s[4][4] = {};
        #pragma unroll 8
        for (int d = 0; d < 64; d++) {
            float4 a = *(const float4*)(Qt + d * 68 + ty * 4);
            float4 b = *(const float4*)(Kt + d * 68 + tx * 4);
            float av[4] = {a.x, a.y, a.z, a.w};
            float bv[4] = {b.x, b.y, b.z, b.w};
            #pragma unroll
            for (int ii = 0; ii < 4; ii++)
                #pragma unroll
                for (int jj = 0; jj < 4; jj++)
                    s[ii][jj] += av[ii] * bv[jj];
        }

        // Online softmax update per row (16 lanes per row share via shfl.xor).
        #pragma unroll
        for (int ii = 0; ii < 4; ii++) {
            float rm = -1e30f;
            #pragma unroll
            for (int jj = 0; jj < 4; jj++) {
                s[ii][jj] *= ATT_SCALE;
                rm = fmaxf(rm, s[ii][jj]);
            }
            #pragma unroll
            for (int off = 8; off >= 1; off >>= 1)
                rm = fmaxf(rm, __shfl_xor_sync(0xffffffffu, rm, off));
            float mnew = fmaxf(mrow[ii], rm);
            float corr = __expf(mrow[ii] - mnew);
            mrow[ii] = mnew;
            float rs = 0.f;
            #pragma unroll
            for (int jj = 0; jj < 4; jj++) {
                float p = __expf(s[ii][jj] - mnew);
                s[ii][jj] = p;
                rs += p;
            }
            #pragma unroll
            for (int off = 8; off >= 1; off >>= 1)
                rs += __shfl_xor_sync(0xffffffffu, rs, off);
            lrow[ii] = lrow[ii] * corr + rs;
            #pragma unroll
            for (int jj = 0; jj < 4; jj++)
                o[ii][jj] *= corr;
        }

        // Write P transposed: Pt[j][i]
        #pragma unroll
        for (int ii = 0; ii < 4; ii++)
            #pragma unroll
            for (int jj = 0; jj < 4; jj++)
                Pt[(tx * 4 + jj) * 68 + (ty * 4 + ii)] = s[ii][jj];
        __syncthreads();

        // O += P @ V
        #pragma unroll 8
        for (int j = 0; j < 64; j++) {
            float4 p = *(const float4*)(Pt + j * 68 + ty * 4);
            float4 v = *(const float4*)(Vs + j * 64 + tx * 4);
            float pv[4] = {p.x, p.y, p.z, p.w};
            float vv[4] = {v.x, v.y, v.z, v.w};
            #pragma unroll
            for (int ii = 0; ii < 4; ii++)
                #pragma unroll
                for (int jj = 0; jj < 4; jj++)
                    o[ii][jj] += pv[ii] * vv[jj];
        }
    }

    #pragma unroll
    for (int ii = 0; ii < 4; ii++) {
        float inv = 1.0f / lrow[ii];
        int row = q0 + ty * 4 + ii;
        #pragma unroll
        for (int jj = 0; jj < 4; jj++)
            Og[(size_t)row * HDIM + tx * 4 + jj] = o[ii][jj] * inv;
    }
}

// ---------------------------------------------------------------------------
// Kernel 3: out = O_perm @ W_proj + b_proj, gathering A from [b,h,n,d] layout.
// ---------------------------------------------------------------------------
__global__ __launch_bounds__(256) void proj_gemm_kernel(
    const float* __restrict__ W,      // [768, 768]
    const float* __restrict__ bias,   // [768]
    float* __restrict__ out)          // [8192, 768]
{
    __shared__ float Ast[16 * 68];
    __shared__ float Bs[16 * 64];

    const int t  = threadIdx.x;
    const int tx = t & 15;
    const int ty = t >> 4;
    const int m0 = blockIdx.y * 64;
    const int n0 = blockIdx.x * 64;

    float acc[4][4] = {};

    for (int kb = 0; kb < EMB; kb += 16) {
        #pragma unroll
        for (int l = 0; l < 4; l++) {
            int idx = t + l * 256;
            int row = idx >> 4, k = idx & 15;
            int m  = m0 + row;
            int bi = m >> 11, ni = m & 2047;
            int kk = kb + k;
            int h  = kk >> 6, d = kk & 63;
            Ast[k * 68 + row] = g_O[((size_t)(bi * NHEAD + h) * SEQ + ni) * HDIM + d];
        }
        #pragma unroll
        for (int l = 0; l < 4; l++) {
            int idx = t + l * 256;
            int k = idx >> 6, n = idx & 63;
            Bs[k * 64 + n] = W[(size_t)(kb + k) * EMB + n0 + n];
        }
        __syncthreads();
        #pragma unroll
        for (int k = 0; k < 16; k++) {
            float4 a = *(const float4*)(Ast + k * 68 + ty * 4);
            float4 b = *(const float4*)(Bs  + k * 64 + tx * 4);
            float av[4] = {a.x, a.y, a.z, a.w};
            float bv[4] = {b.x, b.y, b.z, b.w};
            #pragma unroll
            for (int ii = 0; ii < 4; ii++)
                #pragma unroll
                for (int jj = 0; jj < 4; jj++)
                    acc[ii][jj] += av[ii] * bv[jj];
        }
        __syncthreads();
    }

    #pragma unroll
    for (int ii = 0; ii < 4; ii++) {
        int m = m0 + ty * 4 + ii;
        #pragma unroll
        for (int jj = 0; jj < 4; jj++) {
            int col = n0 + tx * 4 + jj;
            out[(size_t)m * EMB + col] = acc[ii][jj] + bias[col];
        }
    }
}

// ---------------------------------------------------------------------------
// Launch
// ---------------------------------------------------------------------------
extern "C" void kernel_launch(void* const* d_in, const int* in_sizes, int n_in,
                              void* d_out, int out_size)
{
    const float* x      = (const float*)d_in[0];  // [4,2048,768]
    const float* W_qkv  = (const float*)d_in[1];  // [768,2304]
    const float* b_qkv  = (const float*)d_in[2];  // [2304]
    const float* W_proj = (const float*)d_in[3];  // [768,768]
    const float* b_proj = (const float*)d_in[4];  // [768]
    float* out = (float*)d_out;                   // [4,2048,768]

    static bool attr_set = false;
    if (!attr_set) {
        cudaFuncSetAttribute(flash_attn_kernel,
                             cudaFuncAttributeMaxDynamicSharedMemorySize, 68608);
        attr_set = true;
    }

    // 1) QKV GEMM: M=8192, N=2304
    dim3 g1(QKV3 / 64, (BATCH * SEQ) / 64);
    qkv_gemm_kernel<<<g1, 256>>>(x, W_qkv, b_qkv);

    // 2) Flash attention: 32 q-tiles x 48 (b,h)
    dim3 g2(SEQ / 64, BHT);
    flash_attn_kernel<<<g2, 256, 68608>>>();

    // 3) Projection GEMM: M=8192, N=768
    dim3 g3(EMB / 64, (BATCH * SEQ) / 64);
    proj_gemm_kernel<<<g3, 256>>>(W_proj, b_proj, out);
}

// round 4
// speedup vs baseline: 2.8983x; 2.8983x over previous
#include <cuda_runtime.h>

// MultiHeadAttention: b=4, n=2048, emb=768, heads=12, head_dim=64, fp32 in/out.
// tf32 tensor-core pipeline: QKV GEMM -> flash attention -> proj GEMM.

#define EMB    768
#define QKV3   2304
#define NHEAD  12
#define HDIM   64
#define BATCH  4
#define SEQ    2048
#define BHT    (BATCH*NHEAD)
#define ATT_SCALE 0.03608439182435161f   // 1/sqrt(768)

// Scratch (allocation-free rule: __device__ globals).
__device__ float g_Q[BHT * SEQ * HDIM];
__device__ float g_K[BHT * SEQ * HDIM];
__device__ float g_V[BHT * SEQ * HDIM];
__device__ float g_O[BHT * SEQ * HDIM];

// ---------------------------------------------------------------------------
// tf32 helpers
// ---------------------------------------------------------------------------
__device__ __forceinline__ unsigned f2tf(float f) {
    unsigned u;
    asm("cvt.rna.tf32.f32 %0, %1;" : "=r"(u) : "f"(f));
    return u;
}

// D += A * B, m16n8k8 tf32, fp32 accumulate.
__device__ __forceinline__ void mma8(float d[4], const unsigned a[4], const unsigned b[2]) {
    asm volatile(
        "mma.sync.aligned.m16n8k8.row.col.f32.tf32.tf32.f32 "
        "{%0,%1,%2,%3},{%4,%5,%6,%7},{%8,%9},{%0,%1,%2,%3};"
        : "+f"(d[0]), "+f"(d[1]), "+f"(d[2]), "+f"(d[3])
        : "r"(a[0]), "r"(a[1]), "r"(a[2]), "r"(a[3]), "r"(b[0]), "r"(b[1]));
}

// ---------------------------------------------------------------------------
// Kernel 1: qkv = x @ W_qkv + b_qkv, scattered into g_Q/g_K/g_V as [b,h,n,d].
// Block 128x128, BK=32, 8 warps (4x2), warp tile 32x64 (2 m-tiles x 8 n-tiles).
// ---------------------------------------------------------------------------
__global__ __launch_bounds__(256) void qkv_gemm_kernel(
    const float* __restrict__ x,      // [8192, 768]
    const float* __restrict__ W,      // [768, 2304]
    const float* __restrict__ bias)   // [2304]
{
    __shared__ unsigned As[128 * 36];   // [row][k], stride 36 (conflict-free frags)
    __shared__ unsigned Bs[32 * 136];   // [k][col], stride 136

    const int t    = threadIdx.x;
    const int lane = t & 31;
    const int w    = t >> 5;
    const int g    = lane >> 2;     // groupID (0..7)
    const int q    = lane & 3;      // threadID in group
    const int wm   = (w >> 1) * 32; // warp m offset in tile
    const int wn   = (w & 1) * 64;  // warp n offset in tile
    const int m0   = blockIdx.y * 128;
    const int n0   = blockIdx.x * 128;

    float acc[2][8][4] = {};

    for (int kb = 0; kb < EMB; kb += 32) {
        __syncthreads();
        // Load A tile 128x32 (1024 float4)
        #pragma unroll
        for (int l = 0; l < 4; l++) {
            int idx = t + l * 256;
            int row = idx >> 3, k4 = idx & 7;
            float4 v = *(const float4*)&x[(size_t)(m0 + row) * EMB + kb + k4 * 4];
            unsigned* p = &As[row * 36 + k4 * 4];
            p[0] = f2tf(v.x); p[1] = f2tf(v.y); p[2] = f2tf(v.z); p[3] = f2tf(v.w);
        }
        // Load B tile 32x128 (1024 float4)
        #pragma unroll
        for (int l = 0; l < 4; l++) {
            int idx = t + l * 256;
            int k = idx >> 5, c4 = idx & 31;
            float4 v = *(const float4*)&W[(size_t)(kb + k) * QKV3 + n0 + c4 * 4];
            unsigned* p = &Bs[k * 136 + c4 * 4];
            p[0] = f2tf(v.x); p[1] = f2tf(v.y); p[2] = f2tf(v.z); p[3] = f2tf(v.w);
        }
        __syncthreads();

        #pragma unroll
        for (int kk8 = 0; kk8 < 4; kk8++) {
            const int kk = kk8 * 8;
            unsigned a[2][4];
            #pragma unroll
            for (int mt = 0; mt < 2; mt++) {
                int r = wm + mt * 16 + g;
                a[mt][0] = As[r * 36 + kk + q];
                a[mt][1] = As[(r + 8) * 36 + kk + q];
                a[mt][2] = As[r * 36 + kk + q + 4];
                a[mt][3] = As[(r + 8) * 36 + kk + q + 4];
            }
            #pragma unroll
            for (int nt = 0; nt < 8; nt++) {
                unsigned b[2];
                int c = wn + nt * 8 + g;
                b[0] = Bs[(kk + q) * 136 + c];
                b[1] = Bs[(kk + q + 4) * 136 + c];
                mma8(acc[0][nt], a[0], b);
                mma8(acc[1][nt], a[1], b);
            }
        }
    }

    // Scatter epilogue: column j -> h=j/192, d=(j%192)/3, s=j%3 (qkv innermost).
    #pragma unroll
    for (int mt = 0; mt < 2; mt++) {
        #pragma unroll
        for (int nt = 0; nt < 8; nt++) {
            #pragma unroll
            for (int e = 0; e < 4; e++) {
                int row = m0 + wm + mt * 16 + g + ((e >> 1) ? 8 : 0);
                int col = n0 + wn + nt * 8 + 2 * q + (e & 1);
                float v = acc[mt][nt][e] + bias[col];
                int bi = row >> 11, ni = row & 2047;
                int h = col / 192;
                int rem = col - h * 192;
                int d = rem / 3;
                int s = rem - d * 3;
                size_t dst = ((size_t)(bi * NHEAD + h) * SEQ + ni) * HDIM + d;
                if (s == 0)      g_Q[dst] = v;
                else if (s == 1) g_K[dst] = v;
                else             g_V[dst] = v;
            }
        }
    }
}

// ---------------------------------------------------------------------------
// Kernel 2: flash attention, tf32 mma. Block = 128 query rows of one (b,h),
// 8 warps x 16 rows. Streams 32 key tiles of 64. Softmax in fragment layout.
// Dynamic smem: Ps 128x68 + Ks 64x68 + Vs 64x72 (u32) = 70656 B.
// ---------------------------------------------------------------------------
__global__ __launch_bounds__(256) void flash_attn_kernel()
{
    extern __shared__ unsigned sh[];
    unsigned* Ps = sh;               // [row][col] stride 68 (also Q staging)
    unsigned* Ks = Ps + 128 * 68;    // [key][d]   stride 68
    unsigned* Vs = Ks + 64 * 68;     // [key][d]   stride 72

    const int t    = threadIdx.x;
    const int lane = t & 31;
    const int w    = t >> 5;
    const int g    = lane >> 2;
    const int q    = lane & 3;
    const int wrow = w * 16;
    const int bh   = blockIdx.y;
    const int q0   = blockIdx.x * 128;

    const float* Qg = g_Q + (size_t)bh * SEQ * HDIM;
    const float* Kg = g_K + (size_t)bh * SEQ * HDIM;
    const float* Vg = g_V + (size_t)bh * SEQ * HDIM;
    float*       Og = g_O + (size_t)bh * SEQ * HDIM;

    // Stage Q tile (128x64) into Ps, tf32-converted.
    #pragma unroll
    for (int l = 0; l < 8; l++) {
        int idx = t + l * 256;              // 0..2047 float4s
        int row = idx >> 4, c4 = idx & 15;
        float4 v = *(const float4*)&Qg[(size_t)(q0 + row) * HDIM + c4 * 4];
        unsigned* p = &Ps[row * 68 + c4 * 4];
        p[0] = f2tf(v.x); p[1] = f2tf(v.y); p[2] = f2tf(v.z); p[3] = f2tf(v.w);
    }
    __syncthreads();

    // Q A-fragments, persistent in registers (each warp reads its own 16 rows).
    unsigned qf[8][4];
    #pragma unroll
    for (int kc = 0; kc < 8; kc++) {
        int base = (wrow + g) * 68 + kc * 8 + q;
        qf[kc][0] = Ps[base];
        qf[kc][1] = Ps[base + 8 * 68];
        qf[kc][2] = Ps[base + 4];
        qf[kc][3] = Ps[base + 8 * 68 + 4];
    }

    float of[8][4] = {};
    float mr[2] = {-1e30f, -1e30f};
    float lr[2] = {0.f, 0.f};

    for (int kt = 0; kt < SEQ / 64; kt++) {
        __syncthreads();   // all warps done with Ks/Vs of previous iteration
        #pragma unroll
        for (int l = 0; l < 4; l++) {
            int idx = t + l * 256;          // 0..1023 float4s
            int row = idx >> 4, c4 = idx & 15;
            size_t goff = (size_t)(kt * 64 + row) * HDIM + c4 * 4;
            float4 kv = *(const float4*)&Kg[goff];
            float4 vv = *(const float4*)&Vg[goff];
            unsigned* pk = &Ks[row * 68 + c4 * 4];
            pk[0] = f2tf(kv.x); pk[1] = f2tf(kv.y); pk[2] = f2tf(kv.z); pk[3] = f2tf(kv.w);
            unsigned* pv = &Vs[row * 72 + c4 * 4];
            pv[0] = f2tf(vv.x); pv[1] = f2tf(vv.y); pv[2] = f2tf(vv.z); pv[3] = f2tf(vv.w);
        }
        __syncthreads();

        // S = Q @ K^T   (m = 16 query rows, n = 64 keys, k = 64 dims)
        float sf[8][4] = {};
        #pragma unroll
        for (int kc = 0; kc < 8; kc++) {
            #pragma unroll
            for (int nt = 0; nt < 8; nt++) {
                unsigned b[2];
                int krow = (nt * 8 + g) * 68 + kc * 8 + q;
                b[0] = Ks[krow];
                b[1] = Ks[krow + 4];
                mma8(sf[nt], qf[kc], b);
            }
        }
        #pragma unroll
        for (int nt = 0; nt < 8; nt++)
            #pragma unroll
            for (int e = 0; e < 4; e++)
                sf[nt][e] *= ATT_SCALE;

        // Online softmax, per row half (regs {0,1}=row g, {2,3}=row g+8).
        #pragma unroll
        for (int hh = 0; hh < 2; hh++) {
            float rm = -1e30f;
            #pragma unroll
            for (int nt = 0; nt < 8; nt++)
                rm = fmaxf(rm, fmaxf(sf[nt][2 * hh], sf[nt][2 * hh + 1]));
            rm = fmaxf(rm, __shfl_xor_sync(0xffffffffu, rm, 1));
            rm = fmaxf(rm, __shfl_xor_sync(0xffffffffu, rm, 2));
            float mnew = fmaxf(mr[hh], rm);
            float corr = __expf(mr[hh] - mnew);
            mr[hh] = mnew;
            float rs = 0.f;
            #pragma unroll
            for (int nt = 0; nt < 8; nt++) {
                float p0 = __expf(sf[nt][2 * hh] - mnew);
                float p1 = __expf(sf[nt][2 * hh + 1] - mnew);
                sf[nt][2 * hh] = p0;
                sf[nt][2 * hh + 1] = p1;
                rs += p0 + p1;
            }
            rs += __shfl_xor_sync(0xffffffffu, rs, 1);
            rs += __shfl_xor_sync(0xffffffffu, rs, 2);
            lr[hh] = lr[hh] * corr + rs;
            #pragma unroll
            for (int nt = 0; nt < 8; nt++) {
                of[nt][2 * hh] *= corr;
                of[nt][2 * hh + 1] *= corr;
            }
        }

        // Store P to this warp's own rows of Ps (tf32 for next mma).
        #pragma unroll
        for (int nt = 0; nt < 8; nt++) {
            int r0 = (wrow + g) * 68 + nt * 8 + 2 * q;
            Ps[r0]          = f2tf(sf[nt][0]);
            Ps[r0 + 1]      = f2tf(sf[nt][1]);
            Ps[r0 + 8 * 68] = f2tf(sf[nt][2]);
            Ps[r0 + 8 * 68 + 1] = f2tf(sf[nt][3]);
        }
        __syncwarp();

        // O += P @ V   (m = 16 rows, n = 64 dims, k = 64 keys)
        #pragma unroll
        for (int kc = 0; kc < 8; kc++) {
            unsigned pa[4];
            int base = (wrow + g) * 68 + kc * 8 + q;
            pa[0] = Ps[base];
            pa[1] = Ps[base + 8 * 68];
            pa[2] = Ps[base + 4];
            pa[3] = Ps[base + 8 * 68 + 4];
            #pragma unroll
            for (int nt = 0; nt < 8; nt++) {
                unsigned vb[2];
                vb[0] = Vs[(kc * 8 + q) * 72 + nt * 8 + g];
                vb[1] = Vs[(kc * 8 + q + 4) * 72 + nt * 8 + g];
                mma8(of[nt], pa, vb);
            }
        }
        __syncwarp();   // pa reads done before next iteration overwrites Ps
    }

    // Epilogue: normalize and write.
    float inv0 = 1.0f / lr[0];
    float inv1 = 1.0f / lr[1];
    #pragma unroll
    for (int nt = 0; nt < 8; nt++) {
        int r0 = q0 + wrow + g;
        int c  = nt * 8 + 2 * q;
        Og[(size_t)r0 * HDIM + c]           = of[nt][0] * inv0;
        Og[(size_t)r0 * HDIM + c + 1]       = of[nt][1] * inv0;
        Og[(size_t)(r0 + 8) * HDIM + c]     = of[nt][2] * inv1;
        Og[(size_t)(r0 + 8) * HDIM + c + 1] = of[nt][3] * inv1;
    }
}

// ---------------------------------------------------------------------------
// Kernel 3: out = O_perm @ W_proj + b_proj. A gathered from [b,h,n,d] layout.
// Same tiling as kernel 1.
// ---------------------------------------------------------------------------
__global__ __launch_bounds__(256) void proj_gemm_kernel(
    const float* __restrict__ W,      // [768, 768]
    const float* __restrict__ bias,   // [768]
    float* __restrict__ out)          // [8192, 768]
{
    __shared__ unsigned As[128 * 36];
    __shared__ unsigned Bs[32 * 136];

    const int t    = threadIdx.x;
    const int lane = t & 31;
    const int w    = t >> 5;
    const int g    = lane >> 2;
    const int q    = lane & 3;
    const int wm   = (w >> 1) * 32;
    const int wn   = (w & 1) * 64;
    const int m0   = blockIdx.y * 128;
    const int n0   = blockIdx.x * 128;

    float acc[2][8][4] = {};

    for (int kb = 0; kb < EMB; kb += 32) {
        __syncthreads();
        // A tile: row m -> (bi, ni); k col -> (h = k>>6, d = k&63). 4 contiguous d.
        #pragma unroll
        for (int l = 0; l < 4; l++) {
            int idx = t + l * 256;
            int row = idx >> 3, k4 = idx & 7;
            int m = m0 + row;
            int bi = m >> 11, ni = m & 2047;
            int kk = kb + k4 * 4;
            int h = kk >> 6, d = kk & 63;
            float4 v = *(const float4*)&g_O[((size_t)(bi * NHEAD + h) * SEQ + ni) * HDIM + d];
            unsigned* p = &As[row * 36 + k4 * 4];
            p[0] = f2tf(v.x); p[1] = f2tf(v.y); p[2] = f2tf(v.z); p[3] = f2tf(v.w);
        }
        #pragma unroll
        for (int l = 0; l < 4; l++) {
            int idx = t + l * 256;
            int k = idx >> 5, c4 = idx & 31;
            float4 v = *(const float4*)&W[(size_t)(kb + k) * EMB + n0 + c4 * 4];
            unsigned* p = &Bs[k * 136 + c4 * 4];
            p[0] = f2tf(v.x); p[1] = f2tf(v.y); p[2] = f2tf(v.z); p[3] = f2tf(v.w);
        }
        __syncthreads();

        #pragma unroll
        for (int kk8 = 0; kk8 < 4; kk8++) {
            const int kk = kk8 * 8;
            unsigned a[2][4];
            #pragma unroll
            for (int mt = 0; mt < 2; mt++) {
                int r = wm + mt * 16 + g;
                a[mt][0] = As[r * 36 + kk + q];
                a[mt][1] = As[(r + 8) * 36 + kk + q];
                a[mt][2] = As[r * 36 + kk + q + 4];
                a[mt][3] = As[(r + 8) * 36 + kk + q + 4];
            }
            #pragma unroll
            for (int nt = 0; nt < 8; nt++) {
                unsigned b[2];
                int c = wn + nt * 8 + g;
                b[0] = Bs[(kk + q) * 136 + c];
                b[1] = Bs[(kk + q + 4) * 136 + c];
                mma8(acc[0][nt], a[0], b);
                mma8(acc[1][nt], a[1], b);
            }
        }
    }

    #pragma unroll
    for (int mt = 0; mt < 2; mt++) {
        #pragma unroll
        for (int nt = 0; nt < 8; nt++) {
            #pragma unroll
            for (int e = 0; e < 4; e++) {
                int row = m0 + wm + mt * 16 + g + ((e >> 1) ? 8 : 0);
                int col = n0 + wn + nt * 8 + 2 * q + (e & 1);
                out[(size_t)row * EMB + col] = acc[mt][nt][e] + bias[col];
            }
        }
    }
}

// ---------------------------------------------------------------------------
// Launch
// ---------------------------------------------------------------------------
extern "C" void kernel_launch(void* const* d_in, const int* in_sizes, int n_in,
                              void* d_out, int out_size)
{
    const float* x      = (const float*)d_in[0];  // [4,2048,768]
    const float* W_qkv  = (const float*)d_in[1];  // [768,2304]
    const float* b_qkv  = (const float*)d_in[2];  // [2304]
    const float* W_proj = (const float*)d_in[3];  // [768,768]
    const float* b_proj = (const float*)d_in[4];  // [768]
    float* out = (float*)d_out;                   // [4,2048,768]

    static bool attr_set = false;
    if (!attr_set) {
        cudaFuncSetAttribute(flash_attn_kernel,
                             cudaFuncAttributeMaxDynamicSharedMemorySize, 70656);
        attr_set = true;
    }

    // 1) QKV GEMM: M=8192, N=2304
    dim3 g1(QKV3 / 128, (BATCH * SEQ) / 128);
    qkv_gemm_kernel<<<g1, 256>>>(x, W_qkv, b_qkv);

    // 2) Flash attention: 16 q-tiles x 48 (b,h)
    dim3 g2(SEQ / 128, BHT);
    flash_attn_kernel<<<g2, 256, 70656>>>();

    // 3) Projection GEMM: M=8192, N=768
    dim3 g3(EMB / 128, (BATCH * SEQ) / 128);
    proj_gemm_kernel<<<g3, 256>>>(W_proj, b_proj, out);
}

// round 8
// speedup vs baseline: 3.2975x; 1.1377x over previous
#include <cuda_runtime.h>
#include <cstdint>

// MultiHeadAttention: b=4, n=2048, emb=768, heads=12, head_dim=64, fp32 in/out.
// Round 8 (resubmit of R7 after broker infra failure): fp16 m16n8k16 mma.sync
// everywhere (tcgen05 unavailable: harness PTX targets sm_103 without the 'a'
// suffix). fp16 mantissa == tf32 mantissa (10 bits), fp32 accumulate -> same
// accuracy class, 2x rate, half smem traffic.

#define EMB    768
#define QKV3   2304
#define NHEAD  12
#define HDIM   64
#define BATCH  4
#define SEQ    2048
#define BHT    (BATCH*NHEAD)
#define ATT_SCALE 0.03608439182435161f   // 1/sqrt(768)

// Scratch (allocation-free rule: __device__ globals).
__device__ float g_Q[BHT * SEQ * HDIM];
__device__ float g_K[BHT * SEQ * HDIM];
__device__ float g_V[BHT * SEQ * HDIM];
__device__ float g_O[BHT * SEQ * HDIM];
__device__ float g_WqkvT[QKV3 * EMB];    // [N=2304][K=768]
__device__ float g_WprojT[EMB * EMB];    // [N=768][K=768]

// ---------------------------------------------------------------------------
// fp16 helpers
// ---------------------------------------------------------------------------
__device__ __forceinline__ unsigned f2h2(float lo, float hi) {
    unsigned u;
    asm("cvt.rn.f16x2.f32 %0, %1, %2;" : "=r"(u) : "f"(hi), "f"(lo));
    return u;
}

// D += A * B, m16n8k16 fp16 inputs, fp32 accumulate.
__device__ __forceinline__ void mma16(float d[4], const unsigned a[4], const unsigned b[2]) {
    asm volatile(
        "mma.sync.aligned.m16n8k16.row.col.f32.f16.f16.f32 "
        "{%0,%1,%2,%3},{%4,%5,%6,%7},{%8,%9},{%0,%1,%2,%3};"
        : "+f"(d[0]), "+f"(d[1]), "+f"(d[2]), "+f"(d[3])
        : "r"(a[0]), "r"(a[1]), "r"(a[2]), "r"(a[3]), "r"(b[0]), "r"(b[1]));
}

// ---------------------------------------------------------------------------
// Weight transpose kernels: W[K][N] -> Wt[N][K]  (fp32, tiny cost).
// ---------------------------------------------------------------------------
__global__ __launch_bounds__(256) void transpose_qkv_kernel(const float* __restrict__ W) {
    __shared__ float tile[32][33];
    int tx = threadIdx.x & 31, ty = threadIdx.x >> 5;   // 32 x 8
    int n0 = blockIdx.x * 32, k0 = blockIdx.y * 32;
    #pragma unroll
    for (int j = 0; j < 32; j += 8)
        tile[ty + j][tx] = W[(size_t)(k0 + ty + j) * QKV3 + n0 + tx];
    __syncthreads();
    #pragma unroll
    for (int j = 0; j < 32; j += 8)
        g_WqkvT[(size_t)(n0 + ty + j) * EMB + k0 + tx] = tile[tx][ty + j];
}

__global__ __launch_bounds__(256) void transpose_proj_kernel(const float* __restrict__ W) {
    __shared__ float tile[32][33];
    int tx = threadIdx.x & 31, ty = threadIdx.x >> 5;
    int n0 = blockIdx.x * 32, k0 = blockIdx.y * 32;
    #pragma unroll
    for (int j = 0; j < 32; j += 8)
        tile[ty + j][tx] = W[(size_t)(k0 + ty + j) * EMB + n0 + tx];
    __syncthreads();
    #pragma unroll
    for (int j = 0; j < 32; j += 8)
        g_WprojT[(size_t)(n0 + ty + j) * EMB + k0 + tx] = tile[tx][ty + j];
}

// ---------------------------------------------------------------------------
// Kernel 1: qkv = x @ W_qkv + b_qkv -> scatter to g_Q/g_K/g_V [b,h,n,d].
// Block 128x128, K-chunk 64 (32 fp16-pairs, smem row stride 36 u32).
// 8 warps (4x2), warp tile 32x64: 2 m-tiles x 8 n-tiles of m16n8k16.
// ---------------------------------------------------------------------------
__global__ __launch_bounds__(256) void qkv_gemm_kernel(
    const float* __restrict__ x,      // [8192, 768]
    const float* __restrict__ bias)   // [2304]
{
    __shared__ unsigned As[128 * 36];   // [row][kpair], stride 36
    __shared__ unsigned Bs[128 * 36];   // [col][kpair], stride 36

    const int t    = threadIdx.x;
    const int lane = t & 31;
    const int w    = t >> 5;
    const int g    = lane >> 2;
    const int q    = lane & 3;
    const int wm   = (w >> 1) * 32;
    const int wn   = (w & 1) * 64;
    const int m0   = blockIdx.y * 128;
    const int n0   = blockIdx.x * 128;

    const float* Asrc = x + (size_t)m0 * EMB;
    const float* Bsrc = g_WqkvT + (size_t)n0 * EMB;

    float acc[2][8][4] = {};

    for (int kb = 0; kb < EMB / 64; kb++) {
        __syncthreads();
        #pragma unroll
        for (int l = 0; l < 4; l++) {
            int idx = t + l * 256;          // 0..1023: 128 rows x 8 oct-chunks
            int row = idx >> 3, c8 = idx & 7;
            const float* sa = &Asrc[(size_t)row * EMB + kb * 64 + c8 * 8];
            const float* sb = &Bsrc[(size_t)row * EMB + kb * 64 + c8 * 8];
            float4 a0 = *(const float4*)sa, a1 = *(const float4*)(sa + 4);
            float4 b0 = *(const float4*)sb, b1 = *(const float4*)(sb + 4);
            uint4 ua = { f2h2(a0.x,a0.y), f2h2(a0.z,a0.w), f2h2(a1.x,a1.y), f2h2(a1.z,a1.w) };
            uint4 ub = { f2h2(b0.x,b0.y), f2h2(b0.z,b0.w), f2h2(b1.x,b1.y), f2h2(b1.z,b1.w) };
            *(uint4*)&As[row * 36 + c8 * 4] = ua;
            *(uint4*)&Bs[row * 36 + c8 * 4] = ub;
        }
        __syncthreads();

        #pragma unroll
        for (int ks = 0; ks < 4; ks++) {
            const int kk2 = ks * 8;
            unsigned a[2][4];
            #pragma unroll
            for (int mt = 0; mt < 2; mt++) {
                int r = wm + mt * 16 + g;
                a[mt][0] = As[r * 36 + kk2 + q];
                a[mt][1] = As[(r + 8) * 36 + kk2 + q];
                a[mt][2] = As[r * 36 + kk2 + q + 4];
                a[mt][3] = As[(r + 8) * 36 + kk2 + q + 4];
            }
            #pragma unroll
            for (int nt = 0; nt < 8; nt++) {
                int n = wn + nt * 8 + g;
                unsigned b[2];
                b[0] = Bs[n * 36 + kk2 + q];
                b[1] = Bs[n * 36 + kk2 + q + 4];
                mma16(acc[0][nt], a[0], b);
                mma16(acc[1][nt], a[1], b);
            }
        }
    }

    // Scatter: column j -> h=j/192, d=(j%192)/3, s=j%3 (qkv innermost).
    #pragma unroll
    for (int mt = 0; mt < 2; mt++) {
        #pragma unroll
        for (int nt = 0; nt < 8; nt++) {
            #pragma unroll
            for (int e = 0; e < 4; e++) {
                int row = m0 + wm + mt * 16 + g + ((e >> 1) ? 8 : 0);
                int col = n0 + wn + nt * 8 + 2 * q + (e & 1);
                float v = acc[mt][nt][e] + bias[col];
                int bi = row >> 11, ni = row & 2047;
                int h = col / 192;
                int rem = col - h * 192;
                int d = rem / 3;
                int s = rem - d * 3;
                size_t dst = ((size_t)(bi * NHEAD + h) * SEQ + ni) * HDIM + d;
                if (s == 0)      g_Q[dst] = v;
                else if (s == 1) g_K[dst] = v;
                else             g_V[dst] = v;
            }
        }
    }
}

// ---------------------------------------------------------------------------
// Kernel 2: flash attention, fp16 mma. Block = 128 query rows of one (b,h),
// 8 warps x 16 rows, key tiles of 64. Smem (static, 36.9 KB):
//   Qs/Ps [128][36] u32 (Q staged, then per-warp P), Ks [64][36], Vs [64][36].
// Vs is V transposed: Vs[d][keypair] so P@V B-frags are direct loads.
// ---------------------------------------------------------------------------
__global__ __launch_bounds__(256) void flash_attn_kernel()
{
    __shared__ unsigned Qs[128 * 36];   // Q fragments, then P (per-warp rows)
    __shared__ unsigned Ks[64 * 36];    // [key][dpair]
    __shared__ unsigned Vs[64 * 36];    // [d][keypair]

    const int t    = threadIdx.x;
    const int lane = t & 31;
    const int w    = t >> 5;
    const int g    = lane >> 2;
    const int q    = lane & 3;
    const int wrow = w * 16;
    const int bh   = blockIdx.y;
    const int q0   = blockIdx.x * 128;

    const float* Qg = g_Q + (size_t)bh * SEQ * HDIM;
    const float* Kg = g_K + (size_t)bh * SEQ * HDIM;
    const float* Vg = g_V + (size_t)bh * SEQ * HDIM;
    float*       Og = g_O + (size_t)bh * SEQ * HDIM;

    // Stage Q tile (128 x 64) as fp16 pairs.
    #pragma unroll
    for (int l = 0; l < 4; l++) {
        int idx = t + l * 256;              // 128 rows x 8 oct-chunks
        int row = idx >> 3, c8 = idx & 7;
        const float* s = &Qg[(size_t)(q0 + row) * HDIM + c8 * 8];
        float4 v0 = *(const float4*)s, v1 = *(const float4*)(s + 4);
        uint4 u = { f2h2(v0.x,v0.y), f2h2(v0.z,v0.w), f2h2(v1.x,v1.y), f2h2(v1.z,v1.w) };
        *(uint4*)&Qs[row * 36 + c8 * 4] = u;
    }
    __syncthreads();

    // Persistent Q A-fragments (each warp reads its own 16 rows).
    unsigned qf[4][4];
    #pragma unroll
    for (int ks = 0; ks < 4; ks++) {
        int base = (wrow + g) * 36 + ks * 8 + q;
        qf[ks][0] = Qs[base];
        qf[ks][1] = Qs[base + 8 * 36];
        qf[ks][2] = Qs[base + 4];
        qf[ks][3] = Qs[base + 8 * 36 + 4];
    }

    float of[8][4] = {};
    float mr[2] = {-1e30f, -1e30f};
    float lr[2] = {0.f, 0.f};

    for (int kt = 0; kt < SEQ / 64; kt++) {
        const int k0 = kt * 64;
        __syncthreads();   // Ks/Vs reads of previous iteration complete

        // Load K tile (row-aligned) and V tile (transposed to [d][keypair]).
        #pragma unroll
        for (int l = 0; l < 2; l++) {
            int idx = t + l * 256;          // 0..511: 64 keys x 8 oct-chunks
            int key = idx >> 3, c8 = idx & 7;
            const float* s = &Kg[(size_t)(k0 + key) * HDIM + c8 * 8];
            float4 v0 = *(const float4*)s, v1 = *(const float4*)(s + 4);
            uint4 u = { f2h2(v0.x,v0.y), f2h2(v0.z,v0.w), f2h2(v1.x,v1.y), f2h2(v1.z,v1.w) };
            *(uint4*)&Ks[key * 36 + c8 * 4] = u;
        }
        #pragma unroll
        for (int l = 0; l < 2; l++) {
            int idx = t + l * 256;          // 0..511: 32 keypairs x 16 d-quads
            int kp = idx & 31, dq = idx >> 5;
            const float* s0 = &Vg[(size_t)(k0 + 2 * kp) * HDIM + dq * 4];
            const float* s1 = s0 + HDIM;
            float4 v0 = *(const float4*)s0;
            float4 v1 = *(const float4*)s1;
            Vs[(dq * 4 + 0) * 36 + kp] = f2h2(v0.x, v1.x);
            Vs[(dq * 4 + 1) * 36 + kp] = f2h2(v0.y, v1.y);
            Vs[(dq * 4 + 2) * 36 + kp] = f2h2(v0.z, v1.z);
            Vs[(dq * 4 + 3) * 36 + kp] = f2h2(v0.w, v1.w);
        }
        __syncthreads();

        // S = Q @ K^T  (m=16 rows, n=64 keys, k=64 dims; 4 K=16 steps)
        float sf[8][4] = {};
        #pragma unroll
        for (int ks = 0; ks < 4; ks++) {
            #pragma unroll
            for (int nt = 0; nt < 8; nt++) {
                int n = nt * 8 + g;
                unsigned b[2];
                b[0] = Ks[n * 36 + ks * 8 + q];
                b[1] = Ks[n * 36 + ks * 8 + q + 4];
                mma16(sf[nt], qf[ks], b);
            }
        }
        #pragma unroll
        for (int nt = 0; nt < 8; nt++)
            #pragma unroll
            for (int e = 0; e < 4; e++)
                sf[nt][e] *= ATT_SCALE;

        // Online softmax per row half: regs {0,1}=row g, {2,3}=row g+8.
        #pragma unroll
        for (int hh = 0; hh < 2; hh++) {
            float rm = -1e30f;
            #pragma unroll
            for (int nt = 0; nt < 8; nt++)
                rm = fmaxf(rm, fmaxf(sf[nt][2 * hh], sf[nt][2 * hh + 1]));
            rm = fmaxf(rm, __shfl_xor_sync(0xffffffffu, rm, 1));
            rm = fmaxf(rm, __shfl_xor_sync(0xffffffffu, rm, 2));
            float mnew = fmaxf(mr[hh], rm);
            float corr = __expf(mr[hh] - mnew);
            mr[hh] = mnew;
            float rs = 0.f;
            #pragma unroll
            for (int nt = 0; nt < 8; nt++) {
                float p0 = __expf(sf[nt][2 * hh] - mnew);
                float p1 = __expf(sf[nt][2 * hh + 1] - mnew);
                sf[nt][2 * hh] = p0;
                sf[nt][2 * hh + 1] = p1;
                rs += p0 + p1;
            }
            rs += __shfl_xor_sync(0xffffffffu, rs, 1);
            rs += __shfl_xor_sync(0xffffffffu, rs, 2);
            lr[hh] = lr[hh] * corr + rs;
            #pragma unroll
            for (int nt = 0; nt < 8; nt++) {
                of[nt][2 * hh] *= corr;
                of[nt][2 * hh + 1] *= corr;
            }
        }

        // Pack P to fp16 pairs into this warp's own rows of Qs (cols 2q,2q+1
        // are an aligned pair -> single u32 store each).
        #pragma unroll
        for (int nt = 0; nt < 8; nt++) {
            Qs[(wrow + g) * 36 + nt * 4 + q]     = f2h2(sf[nt][0], sf[nt][1]);
            Qs[(wrow + g + 8) * 36 + nt * 4 + q] = f2h2(sf[nt][2], sf[nt][3]);
        }
        __syncwarp();

        // O += P @ V  (m=16 rows, n=64 dims, k=64 keys; 4 K=16 steps)
        #pragma unroll
        for (int ks = 0; ks < 4; ks++) {
            unsigned pa[4];
            int base = (wrow + g) * 36 + ks * 8 + q;
            pa[0] = Qs[base];
            pa[1] = Qs[base + 8 * 36];
            pa[2] = Qs[base + 4];
            pa[3] = Qs[base + 8 * 36 + 4];
            #pragma unroll
            for (int nt = 0; nt < 8; nt++) {
                int n = nt * 8 + g;
                unsigned vb[2];
                vb[0] = Vs[n * 36 + ks * 8 + q];
                vb[1] = Vs[n * 36 + ks * 8 + q + 4];
                mma16(of[nt], pa, vb);
            }
        }
        __syncwarp();   // P reads done before next tile's writes
    }

    float inv0 = 1.0f / lr[0];
    float inv1 = 1.0f / lr[1];
    #pragma unroll
    for (int nt = 0; nt < 8; nt++) {
        int r0 = q0 + wrow + g;
        int c  = nt * 8 + 2 * q;
        Og[(size_t)r0 * HDIM + c]           = of[nt][0] * inv0;
        Og[(size_t)r0 * HDIM + c + 1]       = of[nt][1] * inv0;
        Og[(size_t)(r0 + 8) * HDIM + c]     = of[nt][2] * inv1;
        Og[(size_t)(r0 + 8) * HDIM + c + 1] = of[nt][3] * inv1;
    }
}

// ---------------------------------------------------------------------------
// Kernel 3: out = O_perm @ W_proj + b_proj (A gathered from [b,h,n,d]).
// K-chunk 64 == one head: h = kb, d = c8*8.
// ---------------------------------------------------------------------------
__global__ __launch_bounds__(256) void proj_gemm_kernel(
    const float* __restrict__ bias,   // [768]
    float* __restrict__ out)          // [8192, 768]
{
    __shared__ unsigned As[128 * 36];
    __shared__ unsigned Bs[128 * 36];

    const int t    = threadIdx.x;
    const int lane = t & 31;
    const int w    = t >> 5;
    const int g    = lane >> 2;
    const int q    = lane & 3;
    const int wm   = (w >> 1) * 32;
    const int wn   = (w & 1) * 64;
    const int m0   = blockIdx.y * 128;
    const int n0   = blockIdx.x * 128;

    const float* Bsrc = g_WprojT + (size_t)n0 * EMB;

    float acc[2][8][4] = {};

    for (int kb = 0; kb < EMB / 64; kb++) {
        __syncthreads();
        #pragma unroll
        for (int l = 0; l < 4; l++) {
            int idx = t + l * 256;
            int row = idx >> 3, c8 = idx & 7;
            int m  = m0 + row;
            int bi = m >> 11, ni = m & 2047;
            const float* sa = &g_O[((size_t)(bi * NHEAD + kb) * SEQ + ni) * HDIM + c8 * 8];
            const float* sb = &Bsrc[(size_t)row * EMB + kb * 64 + c8 * 8];
            float4 a0 = *(const float4*)sa, a1 = *(const float4*)(sa + 4);
            float4 b0 = *(const float4*)sb, b1 = *(const float4*)(sb + 4);
            uint4 ua = { f2h2(a0.x,a0.y), f2h2(a0.z,a0.w), f2h2(a1.x,a1.y), f2h2(a1.z,a1.w) };
            uint4 ub = { f2h2(b0.x,b0.y), f2h2(b0.z,b0.w), f2h2(b1.x,b1.y), f2h2(b1.z,b1.w) };
            *(uint4*)&As[row * 36 + c8 * 4] = ua;
            *(uint4*)&Bs[row * 36 + c8 * 4] = ub;
        }
        __syncthreads();

        #pragma unroll
        for (int ks = 0; ks < 4; ks++) {
            const int kk2 = ks * 8;
            unsigned a[2][4];
            #pragma unroll
            for (int mt = 0; mt < 2; mt++) {
                int r = wm + mt * 16 + g;
                a[mt][0] = As[r * 36 + kk2 + q];
                a[mt][1] = As[(r + 8) * 36 + kk2 + q];
                a[mt][2] = As[r * 36 + kk2 + q + 4];
                a[mt][3] = As[(r + 8) * 36 + kk2 + q + 4];
            }
            #pragma unroll
            for (int nt = 0; nt < 8; nt++) {
                int n = wn + nt * 8 + g;
                unsigned b[2];
                b[0] = Bs[n * 36 + kk2 + q];
                b[1] = Bs[n * 36 + kk2 + q + 4];
                mma16(acc[0][nt], a[0], b);
                mma16(acc[1][nt], a[1], b);
            }
        }
    }

    #pragma unroll
    for (int mt = 0; mt < 2; mt++) {
        #pragma unroll
        for (int nt = 0; nt < 8; nt++) {
            #pragma unroll
            for (int e = 0; e < 4; e++) {
                int row = m0 + wm + mt * 16 + g + ((e >> 1) ? 8 : 0);
                int col = n0 + wn + nt * 8 + 2 * q + (e & 1);
                out[(size_t)row * EMB + col] = acc[mt][nt][e] + bias[col];
            }
        }
    }
}

// ---------------------------------------------------------------------------
// Launch
// ---------------------------------------------------------------------------
extern "C" void kernel_launch(void* const* d_in, const int* in_sizes, int n_in,
                              void* d_out, int out_size)
{
    const float* x      = (const float*)d_in[0];  // [4,2048,768]
    const float* W_qkv  = (const float*)d_in[1];  // [768,2304]
    const float* b_qkv  = (const float*)d_in[2];  // [2304]
    const float* W_proj = (const float*)d_in[3];  // [768,768]
    const float* b_proj = (const float*)d_in[4];  // [768]
    float* out = (float*)d_out;                   // [4,2048,768]

    // 0) Weight transposes to K-major [N][K]
    transpose_qkv_kernel<<<dim3(QKV3 / 32, EMB / 32), 256>>>(W_qkv);
    transpose_proj_kernel<<<dim3(EMB / 32, EMB / 32), 256>>>(W_proj);

    // 1) QKV GEMM: M=8192, N=2304
    qkv_gemm_kernel<<<dim3(QKV3 / 128, (BATCH * SEQ) / 128), 256>>>(x, b_qkv);

    // 2) Flash attention: 16 q-tiles x 48 (b,h)
    flash_attn_kernel<<<dim3(SEQ / 128, BHT), 256>>>();

    // 3) Projection GEMM: M=8192, N=768
    proj_gemm_kernel<<<dim3(EMB / 128, (BATCH * SEQ) / 128), 256>>>(b_proj, out);
}

// round 9
// speedup vs baseline: 5.2302x; 1.5861x over previous
#include <cuda_runtime.h>
#include <cuda_fp16.h>
#include <cstdint>

// MultiHeadAttention: b=4, n=2048, emb=768, heads=12, head_dim=64, fp32 in/out.
// Round 9: fp16 m16n8k16 mma.sync; fp16-resident intermediates (Q/K/O fp16,
// V stored transposed [d][seq] fp16, weights fp16 [N][K]); launch_bounds(256,2)
// to fix the 1-CTA/SM occupancy limit seen in round 8 (regs=130 -> occ 12.5%).

#define EMB    768
#define QKV3   2304
#define NHEAD  12
#define HDIM   64
#define BATCH  4
#define SEQ    2048
#define BHT    (BATCH*NHEAD)
#define ATT_SCALE 0.03608439182435161f   // 1/sqrt(768)

// Scratch (allocation-free rule: __device__ globals). All fp16.
__device__ __half g_Qh[BHT * SEQ * HDIM];
__device__ __half g_Kh[BHT * SEQ * HDIM];
__device__ __half g_Vth[BHT * HDIM * SEQ];   // V transposed: [bh][d][seq]
__device__ __half g_Oh[BHT * SEQ * HDIM];
__device__ __half g_WqkvTh[QKV3 * EMB];      // [N=2304][K=768] fp16
__device__ __half g_WprojTh[EMB * EMB];      // [N=768][K=768] fp16

// ---------------------------------------------------------------------------
// fp16 helpers
// ---------------------------------------------------------------------------
__device__ __forceinline__ unsigned f2h2(float lo, float hi) {
    unsigned u;
    asm("cvt.rn.f16x2.f32 %0, %1, %2;" : "=r"(u) : "f"(hi), "f"(lo));
    return u;
}

// D += A * B, m16n8k16 fp16 inputs, fp32 accumulate.
__device__ __forceinline__ void mma16(float d[4], const unsigned a[4], const unsigned b[2]) {
    asm volatile(
        "mma.sync.aligned.m16n8k16.row.col.f32.f16.f16.f32 "
        "{%0,%1,%2,%3},{%4,%5,%6,%7},{%8,%9},{%0,%1,%2,%3};"
        : "+f"(d[0]), "+f"(d[1]), "+f"(d[2]), "+f"(d[3])
        : "r"(a[0]), "r"(a[1]), "r"(a[2]), "r"(a[3]), "r"(b[0]), "r"(b[1]));
}

// ---------------------------------------------------------------------------
// Weight transpose kernels: W[K][N] fp32 -> Wt[N][K] fp16.
// ---------------------------------------------------------------------------
__global__ __launch_bounds__(256) void transpose_qkv_kernel(const float* __restrict__ W) {
    __shared__ float tile[32][33];
    int tx = threadIdx.x & 31, ty = threadIdx.x >> 5;   // 32 x 8
    int n0 = blockIdx.x * 32, k0 = blockIdx.y * 32;
    #pragma unroll
    for (int j = 0; j < 32; j += 8)
        tile[ty + j][tx] = W[(size_t)(k0 + ty + j) * QKV3 + n0 + tx];
    __syncthreads();
    #pragma unroll
    for (int j = 0; j < 32; j += 8)
        g_WqkvTh[(size_t)(n0 + ty + j) * EMB + k0 + tx] = __float2half(tile[tx][ty + j]);
}

__global__ __launch_bounds__(256) void transpose_proj_kernel(const float* __restrict__ W) {
    __shared__ float tile[32][33];
    int tx = threadIdx.x & 31, ty = threadIdx.x >> 5;
    int n0 = blockIdx.x * 32, k0 = blockIdx.y * 32;
    #pragma unroll
    for (int j = 0; j < 32; j += 8)
        tile[ty + j][tx] = W[(size_t)(k0 + ty + j) * EMB + n0 + tx];
    __syncthreads();
    #pragma unroll
    for (int j = 0; j < 32; j += 8)
        g_WprojTh[(size_t)(n0 + ty + j) * EMB + k0 + tx] = __float2half(tile[tx][ty + j]);
}

// ---------------------------------------------------------------------------
// Kernel 1: qkv = x @ W_qkv + b_qkv -> scatter fp16 to g_Qh/g_Kh/g_Vth.
// Block 128x128, K-chunk 64 (32 u32 pairs, smem stride 36).
// 8 warps (4x2), warp tile 32x64: 2 m-tiles x 8 n-tiles of m16n8k16.
// ---------------------------------------------------------------------------
__global__ __launch_bounds__(256, 2) void qkv_gemm_kernel(
    const float* __restrict__ x,      // [8192, 768] fp32
    const float* __restrict__ bias)   // [2304]
{
    __shared__ unsigned As[128 * 36];   // [row][kpair]
    __shared__ unsigned Bs[128 * 36];   // [col][kpair]

    const int t    = threadIdx.x;
    const int lane = t & 31;
    const int w    = t >> 5;
    const int g    = lane >> 2;
    const int q    = lane & 3;
    const int wm   = (w >> 1) * 32;
    const int wn   = (w & 1) * 64;
    const int m0   = blockIdx.y * 128;
    const int n0   = blockIdx.x * 128;

    const float*  Asrc = x + (size_t)m0 * EMB;
    const __half* Bsrc = g_WqkvTh + (size_t)n0 * EMB;

    float acc[2][8][4] = {};

    for (int kb = 0; kb < EMB / 64; kb++) {
        __syncthreads();
        #pragma unroll
        for (int l = 0; l < 4; l++) {
            int idx = t + l * 256;          // 0..1023: 128 rows x 8 oct-chunks
            int row = idx >> 3, c8 = idx & 7;
            const float* sa = &Asrc[(size_t)row * EMB + kb * 64 + c8 * 8];
            float4 a0 = *(const float4*)sa, a1 = *(const float4*)(sa + 4);
            uint4 ua = { f2h2(a0.x,a0.y), f2h2(a0.z,a0.w), f2h2(a1.x,a1.y), f2h2(a1.z,a1.w) };
            uint4 ub = *(const uint4*)&Bsrc[(size_t)row * EMB + kb * 64 + c8 * 8];
            *(uint4*)&As[row * 36 + c8 * 4] = ua;
            *(uint4*)&Bs[row * 36 + c8 * 4] = ub;
        }
        __syncthreads();

        #pragma unroll
        for (int ks = 0; ks < 4; ks++) {
            const int kk2 = ks * 8;
            unsigned a[2][4];
            #pragma unroll
            for (int mt = 0; mt < 2; mt++) {
                int r = wm + mt * 16 + g;
                a[mt][0] = As[r * 36 + kk2 + q];
                a[mt][1] = As[(r + 8) * 36 + kk2 + q];
                a[mt][2] = As[r * 36 + kk2 + q + 4];
                a[mt][3] = As[(r + 8) * 36 + kk2 + q + 4];
            }
            #pragma unroll
            for (int nt = 0; nt < 8; nt++) {
                int n = wn + nt * 8 + g;
                unsigned b[2];
                b[0] = Bs[n * 36 + kk2 + q];
                b[1] = Bs[n * 36 + kk2 + q + 4];
                mma16(acc[0][nt], a[0], b);
                mma16(acc[1][nt], a[1], b);
            }
        }
    }

    // Scatter: column j -> h=j/192, d=(j%192)/3, s=j%3 (qkv innermost).
    // Q/K stored [bh][n][d]; V stored transposed [bh][d][n].
    #pragma unroll
    for (int mt = 0; mt < 2; mt++) {
        #pragma unroll
        for (int nt = 0; nt < 8; nt++) {
            #pragma unroll
            for (int e = 0; e < 4; e++) {
                int row = m0 + wm + mt * 16 + g + ((e >> 1) ? 8 : 0);
                int col = n0 + wn + nt * 8 + 2 * q + (e & 1);
                float v = acc[mt][nt][e] + bias[col];
                int bi = row >> 11, ni = row & 2047;
                int h = col / 192;
                int rem = col - h * 192;
                int d = rem / 3;
                int s = rem - d * 3;
                __half hv = __float2half(v);
                if (s == 0)
                    g_Qh[((size_t)(bi * NHEAD + h) * SEQ + ni) * HDIM + d] = hv;
                else if (s == 1)
                    g_Kh[((size_t)(bi * NHEAD + h) * SEQ + ni) * HDIM + d] = hv;
                else
                    g_Vth[((size_t)(bi * NHEAD + h) * HDIM + d) * SEQ + ni] = hv;
            }
        }
    }
}

// ---------------------------------------------------------------------------
// Kernel 2: flash attention, fp16 mma. Block = 128 query rows of one (b,h),
// 8 warps x 16 rows, key tiles of 64. Smem 36.9 KB:
//   Qs/Ps [128][36] (Q staged, then per-warp P), Ks [64][36], Vs [64][36].
// Vs[d][keypair] loaded straight from g_Vth (contiguous rows, pre-paired).
// ---------------------------------------------------------------------------
__global__ __launch_bounds__(256, 2) void flash_attn_kernel()
{
    __shared__ unsigned Qs[128 * 36];   // Q fragments, then P (per-warp rows)
    __shared__ unsigned Ks[64 * 36];    // [key][dpair]
    __shared__ unsigned Vs[64 * 36];    // [d][keypair]

    const int t    = threadIdx.x;
    const int lane = t & 31;
    const int w    = t >> 5;
    const int g    = lane >> 2;
    const int q    = lane & 3;
    const int wrow = w * 16;
    const int bh   = blockIdx.y;
    const int q0   = blockIdx.x * 128;

    const __half* Qg  = g_Qh  + (size_t)bh * SEQ * HDIM;
    const __half* Kg  = g_Kh  + (size_t)bh * SEQ * HDIM;
    const __half* Vtg = g_Vth + (size_t)bh * HDIM * SEQ;
    __half*       Og  = g_Oh  + (size_t)bh * SEQ * HDIM;

    // Stage Q tile (128 x 64 halves) — direct uint4 copies.
    #pragma unroll
    for (int l = 0; l < 4; l++) {
        int idx = t + l * 256;              // 128 rows x 8 oct-chunks
        int row = idx >> 3, c8 = idx & 7;
        uint4 u = *(const uint4*)&Qg[(size_t)(q0 + row) * HDIM + c8 * 8];
        *(uint4*)&Qs[row * 36 + c8 * 4] = u;
    }
    __syncthreads();

    // Persistent Q A-fragments (each warp reads its own 16 rows).
    unsigned qf[4][4];
    #pragma unroll
    for (int ks = 0; ks < 4; ks++) {
        int base = (wrow + g) * 36 + ks * 8 + q;
        qf[ks][0] = Qs[base];
        qf[ks][1] = Qs[base + 8 * 36];
        qf[ks][2] = Qs[base + 4];
        qf[ks][3] = Qs[base + 8 * 36 + 4];
    }

    float of[8][4] = {};
    float mr[2] = {-1e30f, -1e30f};
    float lr[2] = {0.f, 0.f};

    for (int kt = 0; kt < SEQ / 64; kt++) {
        const int k0 = kt * 64;
        __syncthreads();   // Ks/Vs reads of previous iteration complete

        // K tile: [key][dpair], direct copy. V tile: [d][keypair], direct copy
        // from transposed global (keys 2kp,2kp+1 are adjacent halves -> pair).
        #pragma unroll
        for (int l = 0; l < 2; l++) {
            int idx = t + l * 256;          // 0..511: 64 rows x 8 oct-chunks
            int row = idx >> 3, c8 = idx & 7;
            uint4 uk = *(const uint4*)&Kg[(size_t)(k0 + row) * HDIM + c8 * 8];
            *(uint4*)&Ks[row * 36 + c8 * 4] = uk;
            uint4 uv = *(const uint4*)&Vtg[(size_t)row * SEQ + k0 + c8 * 8];
            *(uint4*)&Vs[row * 36 + c8 * 4] = uv;
        }
        __syncthreads();

        // S = Q @ K^T  (m=16 rows, n=64 keys, k=64 dims; 4 K=16 steps)
        float sf[8][4] = {};
        #pragma unroll
        for (int ks = 0; ks < 4; ks++) {
            #pragma unroll
            for (int nt = 0; nt < 8; nt++) {
                int n = nt * 8 + g;
                unsigned b[2];
                b[0] = Ks[n * 36 + ks * 8 + q];
                b[1] = Ks[n * 36 + ks * 8 + q + 4];
                mma16(sf[nt], qf[ks], b);
            }
        }
        #pragma unroll
        for (int nt = 0; nt < 8; nt++)
            #pragma unroll
            for (int e = 0; e < 4; e++)
                sf[nt][e] *= ATT_SCALE;

        // Online softmax per row half: regs {0,1}=row g, {2,3}=row g+8.
        #pragma unroll
        for (int hh = 0; hh < 2; hh++) {
            float rm = -1e30f;
            #pragma unroll
            for (int nt = 0; nt < 8; nt++)
                rm = fmaxf(rm, fmaxf(sf[nt][2 * hh], sf[nt][2 * hh + 1]));
            rm = fmaxf(rm, __shfl_xor_sync(0xffffffffu, rm, 1));
            rm = fmaxf(rm, __shfl_xor_sync(0xffffffffu, rm, 2));
            float mnew = fmaxf(mr[hh], rm);
            float corr = __expf(mr[hh] - mnew);
            mr[hh] = mnew;
            float rs = 0.f;
            #pragma unroll
            for (int nt = 0; nt < 8; nt++) {
                float p0 = __expf(sf[nt][2 * hh] - mnew);
                float p1 = __expf(sf[nt][2 * hh + 1] - mnew);
                sf[nt][2 * hh] = p0;
                sf[nt][2 * hh + 1] = p1;
                rs += p0 + p1;
            }
            rs += __shfl_xor_sync(0xffffffffu, rs, 1);
            rs += __shfl_xor_sync(0xffffffffu, rs, 2);
            lr[hh] = lr[hh] * corr + rs;
            #pragma unroll
            for (int nt = 0; nt < 8; nt++) {
                of[nt][2 * hh] *= corr;
                of[nt][2 * hh + 1] *= corr;
            }
        }

        // Pack P to fp16 pairs into this warp's own rows of Qs.
        #pragma unroll
        for (int nt = 0; nt < 8; nt++) {
            Qs[(wrow + g) * 36 + nt * 4 + q]     = f2h2(sf[nt][0], sf[nt][1]);
            Qs[(wrow + g + 8) * 36 + nt * 4 + q] = f2h2(sf[nt][2], sf[nt][3]);
        }
        __syncwarp();

        // O += P @ V  (m=16 rows, n=64 dims, k=64 keys; 4 K=16 steps)
        #pragma unroll
        for (int ks = 0; ks < 4; ks++) {
            unsigned pa[4];
            int base = (wrow + g) * 36 + ks * 8 + q;
            pa[0] = Qs[base];
            pa[1] = Qs[base + 8 * 36];
            pa[2] = Qs[base + 4];
            pa[3] = Qs[base + 8 * 36 + 4];
            #pragma unroll
            for (int nt = 0; nt < 8; nt++) {
                int n = nt * 8 + g;
                unsigned vb[2];
                vb[0] = Vs[n * 36 + ks * 8 + q];
                vb[1] = Vs[n * 36 + ks * 8 + q + 4];
                mma16(of[nt], pa, vb);
            }
        }
        __syncwarp();   // P reads done before next tile's writes
    }

    // Epilogue: normalize, pack to fp16 pairs, one u32 store per pair.
    float inv0 = 1.0f / lr[0];
    float inv1 = 1.0f / lr[1];
    #pragma unroll
    for (int nt = 0; nt < 8; nt++) {
        int r0 = q0 + wrow + g;
        int c  = nt * 8 + 2 * q;
        *(unsigned*)&Og[(size_t)r0 * HDIM + c] =
            f2h2(of[nt][0] * inv0, of[nt][1] * inv0);
        *(unsigned*)&Og[(size_t)(r0 + 8) * HDIM + c] =
            f2h2(of[nt][2] * inv1, of[nt][3] * inv1);
    }
}

// ---------------------------------------------------------------------------
// Kernel 3: out = O_perm @ W_proj + b_proj (A gathered fp16 from [b,h,n,d]).
// K-chunk 64 == one head: h = kb.
// ---------------------------------------------------------------------------
__global__ __launch_bounds__(256, 2) void proj_gemm_kernel(
    const float* __restrict__ bias,   // [768]
    float* __restrict__ out)          // [8192, 768] fp32
{
    __shared__ unsigned As[128 * 36];
    __shared__ unsigned Bs[128 * 36];

    const int t    = threadIdx.x;
    const int lane = t & 31;
    const int w    = t >> 5;
    const int g    = lane >> 2;
    const int q    = lane & 3;
    const int wm   = (w >> 1) * 32;
    const int wn   = (w & 1) * 64;
    const int m0   = blockIdx.y * 128;
    const int n0   = blockIdx.x * 128;

    const __half* Bsrc = g_WprojTh + (size_t)n0 * EMB;

    float acc[2][8][4] = {};

    for (int kb = 0; kb < EMB / 64; kb++) {
        __syncthreads();
        #pragma unroll
        for (int l = 0; l < 4; l++) {
            int idx = t + l * 256;
            int row = idx >> 3, c8 = idx & 7;
            int m  = m0 + row;
            int bi = m >> 11, ni = m & 2047;
            uint4 ua = *(const uint4*)
                &g_Oh[((size_t)(bi * NHEAD + kb) * SEQ + ni) * HDIM + c8 * 8];
            uint4 ub = *(const uint4*)&Bsrc[(size_t)row * EMB + kb * 64 + c8 * 8];
            *(uint4*)&As[row * 36 + c8 * 4] = ua;
            *(uint4*)&Bs[row * 36 + c8 * 4] = ub;
        }
        __syncthreads();

        #pragma unroll
        for (int ks = 0; ks < 4; ks++) {
            const int kk2 = ks * 8;
            unsigned a[2][4];
            #pragma unroll
            for (int mt = 0; mt < 2; mt++) {
                int r = wm + mt * 16 + g;
                a[mt][0] = As[r * 36 + kk2 + q];
                a[mt][1] = As[(r + 8) * 36 + kk2 + q];
                a[mt][2] = As[r * 36 + kk2 + q + 4];
                a[mt][3] = As[(r + 8) * 36 + kk2 + q + 4];
            }
            #pragma unroll
            for (int nt = 0; nt < 8; nt++) {
                int n = wn + nt * 8 + g;
                unsigned b[2];
                b[0] = Bs[n * 36 + kk2 + q];
                b[1] = Bs[n * 36 + kk2 + q + 4];
                mma16(acc[0][nt], a[0], b);
                mma16(acc[1][nt], a[1], b);
            }
        }
    }

    #pragma unroll
    for (int mt = 0; mt < 2; mt++) {
        #pragma unroll
        for (int nt = 0; nt < 8; nt++) {
            #pragma unroll
            for (int e = 0; e < 4; e++) {
                int row = m0 + wm + mt * 16 + g + ((e >> 1) ? 8 : 0);
                int col = n0 + wn + nt * 8 + 2 * q + (e & 1);
                out[(size_t)row * EMB + col] = acc[mt][nt][e] + bias[col];
            }
        }
    }
}

// ---------------------------------------------------------------------------
// Launch
// ---------------------------------------------------------------------------
extern "C" void kernel_launch(void* const* d_in, const int* in_sizes, int n_in,
                              void* d_out, int out_size)
{
    const float* x      = (const float*)d_in[0];  // [4,2048,768]
    const float* W_qkv  = (const float*)d_in[1];  // [768,2304]
    const float* b_qkv  = (const float*)d_in[2];  // [2304]
    const float* W_proj = (const float*)d_in[3];  // [768,768]
    const float* b_proj = (const float*)d_in[4];  // [768]
    float* out = (float*)d_out;                   // [4,2048,768]

    // 0) Weight transposes to fp16 K-major [N][K]
    transpose_qkv_kernel<<<dim3(QKV3 / 32, EMB / 32), 256>>>(W_qkv);
    transpose_proj_kernel<<<dim3(EMB / 32, EMB / 32), 256>>>(W_proj);

    // 1) QKV GEMM: M=8192, N=2304
    qkv_gemm_kernel<<<dim3(QKV3 / 128, (BATCH * SEQ) / 128), 256>>>(x, b_qkv);

    // 2) Flash attention: 16 q-tiles x 48 (b,h)
    flash_attn_kernel<<<dim3(SEQ / 128, BHT), 256>>>();

    // 3) Projection GEMM: M=8192, N=768
    proj_gemm_kernel<<<dim3(EMB / 128, (BATCH * SEQ) / 128), 256>>>(b_proj, out);
}

// round 11
// speedup vs baseline: 5.5244x; 1.0562x over previous
#include <cuda_runtime.h>
#include <cuda_fp16.h>
#include <cstdint>

// MultiHeadAttention: b=4, n=2048, emb=768, heads=12, head_dim=64, fp32 in/out.
// Round 10: fp16 m16n8k16 + ldmatrix/stmatrix fragment movement + hoisted
// smem addresses + exp2-domain softmax. fp16-resident intermediates.

#define EMB    768
#define QKV3   2304
#define NHEAD  12
#define HDIM   64
#define BATCH  4
#define SEQ    2048
#define BHT    (BATCH*NHEAD)
#define ATT_SCALE2 0.052060088278316,/* placeholder avoided */
#undef ATT_SCALE2
// 1/sqrt(768) * log2(e)
#define ATT_SCALE_LOG2E 0.05206022387508899f

// Scratch (allocation-free rule: __device__ globals). All fp16.
__device__ __half g_Qh[BHT * SEQ * HDIM];
__device__ __half g_Kh[BHT * SEQ * HDIM];
__device__ __half g_Vth[BHT * HDIM * SEQ];   // V transposed: [bh][d][seq]
__device__ __half g_Oh[BHT * SEQ * HDIM];
__device__ __half g_WqkvTh[QKV3 * EMB];      // [N=2304][K=768] fp16
__device__ __half g_WprojTh[EMB * EMB];      // [N=768][K=768] fp16

// ---------------------------------------------------------------------------
// helpers
// ---------------------------------------------------------------------------
__device__ __forceinline__ unsigned f2h2(float lo, float hi) {
    unsigned u;
    asm("cvt.rn.f16x2.f32 %0, %1, %2;" : "=r"(u) : "f"(hi), "f"(lo));
    return u;
}

__device__ __forceinline__ unsigned smem_u32(const void* p) {
    unsigned a;
    asm("{ .reg .u64 t; cvta.to.shared.u64 t, %1; cvt.u32.u64 %0, t; }"
        : "=r"(a) : "l"(p));
    return a;
}

// D += A * B, m16n8k16 fp16 inputs, fp32 accumulate.
__device__ __forceinline__ void mma16(float d[4], const unsigned a[4],
                                      unsigned b0, unsigned b1) {
    asm volatile(
        "mma.sync.aligned.m16n8k16.row.col.f32.f16.f16.f32 "
        "{%0,%1,%2,%3},{%4,%5,%6,%7},{%8,%9},{%0,%1,%2,%3};"
        : "+f"(d[0]), "+f"(d[1]), "+f"(d[2]), "+f"(d[3])
        : "r"(a[0]), "r"(a[1]), "r"(a[2]), "r"(a[3]), "r"(b0), "r"(b1));
}

__device__ __forceinline__ void ldsm_x4(unsigned r[4], unsigned addr) {
    asm volatile("ldmatrix.sync.aligned.m8n8.x4.shared.b16 {%0,%1,%2,%3}, [%4];"
                 : "=r"(r[0]), "=r"(r[1]), "=r"(r[2]), "=r"(r[3]) : "r"(addr));
}

__device__ __forceinline__ void stsm_x4(unsigned addr, unsigned r0, unsigned r1,
                                        unsigned r2, unsigned r3) {
    asm volatile("stmatrix.sync.aligned.m8n8.x4.shared.b16 [%0], {%1,%2,%3,%4};"
                 :: "r"(addr), "r"(r0), "r"(r1), "r"(r2), "r"(r3) : "memory");
}

// Per-lane address helpers for the stride-36-u32 (144 B) smem layout.
// "A-type" x4 (m16 rows x k16): m0 rows+0 col+0, m1 rows+8 col+0,
//                               m2 rows+0 col+4, m3 rows+8 col+4.
// "B-type" x4 (two 8-row n-tiles x k16): m0 ntlow col+0, m1 ntlow col+4,
//                                        m2 nthigh col+0, m3 nthigh col+4.
__device__ __forceinline__ unsigned addr_a(unsigned base, int row0, int lane) {
    int l8 = lane & 7, mh = (lane >> 3) & 1, mq = lane >> 4;
    return base + (unsigned)(((row0 + mh * 8 + l8) * 36 + mq * 4) * 4);
}
__device__ __forceinline__ unsigned addr_b(unsigned base, int row0, int lane) {
    int l8 = lane & 7, m = lane >> 3;
    return base + (unsigned)(((row0 + ((m >> 1) & 1) * 8 + l8) * 36 + (m & 1) * 4) * 4);
}

// ---------------------------------------------------------------------------
// Weight transpose kernels: W[K][N] fp32 -> Wt[N][K] fp16.
// ---------------------------------------------------------------------------
__global__ __launch_bounds__(256) void transpose_qkv_kernel(const float* __restrict__ W) {
    __shared__ float tile[32][33];
    int tx = threadIdx.x & 31, ty = threadIdx.x >> 5;   // 32 x 8
    int n0 = blockIdx.x * 32, k0 = blockIdx.y * 32;
    #pragma unroll
    for (int j = 0; j < 32; j += 8)
        tile[ty + j][tx] = W[(size_t)(k0 + ty + j) * QKV3 + n0 + tx];
    __syncthreads();
    #pragma unroll
    for (int j = 0; j < 32; j += 8)
        g_WqkvTh[(size_t)(n0 + ty + j) * EMB + k0 + tx] = __float2half(tile[tx][ty + j]);
}

__global__ __launch_bounds__(256) void transpose_proj_kernel(const float* __restrict__ W) {
    __shared__ float tile[32][33];
    int tx = threadIdx.x & 31, ty = threadIdx.x >> 5;
    int n0 = blockIdx.x * 32, k0 = blockIdx.y * 32;
    #pragma unroll
    for (int j = 0; j < 32; j += 8)
        tile[ty + j][tx] = W[(size_t)(k0 + ty + j) * EMB + n0 + tx];
    __syncthreads();
    #pragma unroll
    for (int j = 0; j < 32; j += 8)
        g_WprojTh[(size_t)(n0 + ty + j) * EMB + k0 + tx] = __float2half(tile[tx][ty + j]);
}

// ---------------------------------------------------------------------------
// Kernel 1: qkv = x @ W_qkv + b_qkv -> scatter fp16 to g_Qh/g_Kh/g_Vth.
// Block 128x128, K-chunk 64; 8 warps (4x2), warp tile 32x64.
// ---------------------------------------------------------------------------
__global__ __launch_bounds__(256, 2) void qkv_gemm_kernel(
    const float* __restrict__ x,      // [8192, 768] fp32
    const float* __restrict__ bias)   // [2304]
{
    __shared__ unsigned As[128 * 36];
    __shared__ unsigned Bs[128 * 36];

    const int t    = threadIdx.x;
    const int lane = t & 31;
    const int w    = t >> 5;
    const int g    = lane >> 2;
    const int q    = lane & 3;
    const int wm   = (w >> 1) * 32;
    const int wn   = (w & 1) * 64;
    const int m0   = blockIdx.y * 128;
    const int n0   = blockIdx.x * 128;

    const float*  Asrc = x + (size_t)m0 * EMB;
    const __half* Bsrc = g_WqkvTh + (size_t)n0 * EMB;

    // Hoisted per-lane ldmatrix addresses (only +ks*32B varies).
    unsigned As_u = smem_u32(As), Bs_u = smem_u32(Bs);
    unsigned aaddr[2], baddr[4];
    #pragma unroll
    for (int mt = 0; mt < 2; mt++) aaddr[mt] = addr_a(As_u, wm + mt * 16, lane);
    #pragma unroll
    for (int p = 0; p < 4; p++)    baddr[p]  = addr_b(Bs_u, wn + p * 16, lane);

    float acc[2][8][4] = {};

    for (int kb = 0; kb < EMB / 64; kb++) {
        __syncthreads();
        #pragma unroll
        for (int l = 0; l < 4; l++) {
            int idx = t + l * 256;          // 0..1023: 128 rows x 8 oct-chunks
            int row = idx >> 3, c8 = idx & 7;
            const float* sa = &Asrc[(size_t)row * EMB + kb * 64 + c8 * 8];
            float4 a0 = *(const float4*)sa, a1 = *(const float4*)(sa + 4);
            uint4 ua = { f2h2(a0.x,a0.y), f2h2(a0.z,a0.w), f2h2(a1.x,a1.y), f2h2(a1.z,a1.w) };
            uint4 ub = *(const uint4*)&Bsrc[(size_t)row * EMB + kb * 64 + c8 * 8];
            *(uint4*)&As[row * 36 + c8 * 4] = ua;
            *(uint4*)&Bs[row * 36 + c8 * 4] = ub;
        }
        __syncthreads();

        #pragma unroll
        for (int ks = 0; ks < 4; ks++) {
            unsigned a0[4], a1[4];
            ldsm_x4(a0, aaddr[0] + ks * 32);
            ldsm_x4(a1, aaddr[1] + ks * 32);
            #pragma unroll
            for (int p = 0; p < 4; p++) {
                unsigned bb[4];
                ldsm_x4(bb, baddr[p] + ks * 32);
                mma16(acc[0][2 * p],     a0, bb[0], bb[1]);
                mma16(acc[0][2 * p + 1], a0, bb[2], bb[3]);
                mma16(acc[1][2 * p],     a1, bb[0], bb[1]);
                mma16(acc[1][2 * p + 1], a1, bb[2], bb[3]);
            }
        }
    }

    // Scatter: column j -> h=j/192, d=(j%192)/3, s=j%3 (qkv innermost).
    #pragma unroll
    for (int mt = 0; mt < 2; mt++) {
        #pragma unroll
        for (int nt = 0; nt < 8; nt++) {
            #pragma unroll
            for (int e = 0; e < 4; e++) {
                int row = m0 + wm + mt * 16 + g + ((e >> 1) ? 8 : 0);
                int col = n0 + wn + nt * 8 + 2 * q + (e & 1);
                float v = acc[mt][nt][e] + bias[col];
                int bi = row >> 11, ni = row & 2047;
                int h = col / 192;
                int rem = col - h * 192;
                int d = rem / 3;
                int s = rem - d * 3;
                __half hv = __float2half(v);
                if (s == 0)
                    g_Qh[((size_t)(bi * NHEAD + h) * SEQ + ni) * HDIM + d] = hv;
                else if (s == 1)
                    g_Kh[((size_t)(bi * NHEAD + h) * SEQ + ni) * HDIM + d] = hv;
                else
                    g_Vth[((size_t)(bi * NHEAD + h) * HDIM + d) * SEQ + ni] = hv;
            }
        }
    }
}

// ---------------------------------------------------------------------------
// Kernel 2: flash attention. 8 warps x 16 query rows, key tiles of 64.
// All fragment movement via ldmatrix/stmatrix; addresses hoisted.
// ---------------------------------------------------------------------------
__global__ __launch_bounds__(256, 2) void flash_attn_kernel()
{
    __shared__ unsigned Qs[128 * 36];   // Q staged, then per-warp P
    __shared__ unsigned Ks[64 * 36];    // [key][dpair]
    __shared__ unsigned Vs[64 * 36];    // [d][keypair]

    const int t    = threadIdx.x;
    const int lane = t & 31;
    const int w    = t >> 5;
    const int g    = lane >> 2;
    const int q    = lane & 3;
    const int wrow = w * 16;
    const int bh   = blockIdx.y;
    const int q0   = blockIdx.x * 128;

    const __half* Qg  = g_Qh  + (size_t)bh * SEQ * HDIM;
    const __half* Kg  = g_Kh  + (size_t)bh * SEQ * HDIM;
    const __half* Vtg = g_Vth + (size_t)bh * HDIM * SEQ;
    __half*       Og  = g_Oh  + (size_t)bh * SEQ * HDIM;

    unsigned Qs_u = smem_u32(Qs), Ks_u = smem_u32(Ks), Vs_u = smem_u32(Vs);
    const unsigned qaddr = addr_a(Qs_u, wrow, lane);   // also P A-frags
    unsigned kaddr[4], vaddr[4], paddr[4];
    #pragma unroll
    for (int p = 0; p < 4; p++) {
        kaddr[p] = addr_b(Ks_u, p * 16, lane);
        vaddr[p] = addr_b(Vs_u, p * 16, lane);
        // P stmatrix: m0/m1 = nt even rows low/high, m2/m3 = nt odd.
        int l8 = lane & 7, m = lane >> 3;
        paddr[p] = Qs_u + (unsigned)(((wrow + (m & 1) * 8 + l8) * 36
                                      + (m >> 1) * 4 + p * 8) * 4);
    }

    // Stage Q tile (128 x 64 halves) — direct uint4 copies.
    #pragma unroll
    for (int l = 0; l < 4; l++) {
        int idx = t + l * 256;
        int row = idx >> 3, c8 = idx & 7;
        uint4 u = *(const uint4*)&Qg[(size_t)(q0 + row) * HDIM + c8 * 8];
        *(uint4*)&Qs[row * 36 + c8 * 4] = u;
    }
    __syncthreads();

    // Persistent Q A-fragments.
    unsigned qf[4][4];
    #pragma unroll
    for (int ks = 0; ks < 4; ks++) ldsm_x4(qf[ks], qaddr + ks * 32);

    float of[8][4] = {};
    float mr[2] = {-1e30f, -1e30f};
    float lr[2] = {0.f, 0.f};

    for (int kt = 0; kt < SEQ / 64; kt++) {
        const int k0 = kt * 64;
        __syncthreads();   // Ks/Vs reads of previous iteration complete

        #pragma unroll
        for (int l = 0; l < 2; l++) {
            int idx = t + l * 256;          // 0..511: 64 rows x 8 oct-chunks
            int row = idx >> 3, c8 = idx & 7;
            uint4 uk = *(const uint4*)&Kg[(size_t)(k0 + row) * HDIM + c8 * 8];
            *(uint4*)&Ks[row * 36 + c8 * 4] = uk;
            uint4 uv = *(const uint4*)&Vtg[(size_t)row * SEQ + k0 + c8 * 8];
            *(uint4*)&Vs[row * 36 + c8 * 4] = uv;
        }
        __syncthreads();

        // S = Q @ K^T
        float sf[8][4] = {};
        #pragma unroll
        for (int p = 0; p < 4; p++) {
            unsigned bb[4][4];
            #pragma unroll
            for (int ks = 0; ks < 4; ks++) ldsm_x4(bb[ks], kaddr[p] + ks * 32);
            #pragma unroll
            for (int ks = 0; ks < 4; ks++) {
                mma16(sf[2 * p],     qf[ks], bb[ks][0], bb[ks][1]);
                mma16(sf[2 * p + 1], qf[ks], bb[ks][2], bb[ks][3]);
            }
        }
        #pragma unroll
        for (int nt = 0; nt < 8; nt++)
            #pragma unroll
            for (int e = 0; e < 4; e++)
                sf[nt][e] *= ATT_SCALE_LOG2E;   // log2 domain

        // Online softmax (exp2 domain) per row half.
        #pragma unroll
        for (int hh = 0; hh < 2; hh++) {
            float rm = -1e30f;
            #pragma unroll
            for (int nt = 0; nt < 8; nt++)
                rm = fmaxf(rm, fmaxf(sf[nt][2 * hh], sf[nt][2 * hh + 1]));
            rm = fmaxf(rm, __shfl_xor_sync(0xffffffffu, rm, 1));
            rm = fmaxf(rm, __shfl_xor_sync(0xffffffffu, rm, 2));
            float mnew = fmaxf(mr[hh], rm);
            float corr = exp2f(mr[hh] - mnew);
            mr[hh] = mnew;
            float rs = 0.f;
            #pragma unroll
            for (int nt = 0; nt < 8; nt++) {
                float p0 = exp2f(sf[nt][2 * hh] - mnew);
                float p1 = exp2f(sf[nt][2 * hh + 1] - mnew);
                sf[nt][2 * hh] = p0;
                sf[nt][2 * hh + 1] = p1;
                rs += p0 + p1;
            }
            rs += __shfl_xor_sync(0xffffffffu, rs, 1);
            rs += __shfl_xor_sync(0xffffffffu, rs, 2);
            lr[hh] = lr[hh] * corr + rs;
            #pragma unroll
            for (int nt = 0; nt < 8; nt++) {
                of[nt][2 * hh] *= corr;
                of[nt][2 * hh + 1] *= corr;
            }
        }

        // P -> smem via stmatrix (4 x4-stores cover 16 rows x 64 keys).
        #pragma unroll
        for (int p = 0; p < 4; p++) {
            stsm_x4(paddr[p],
                    f2h2(sf[2 * p][0],     sf[2 * p][1]),
                    f2h2(sf[2 * p][2],     sf[2 * p][3]),
                    f2h2(sf[2 * p + 1][0], sf[2 * p + 1][1]),
                    f2h2(sf[2 * p + 1][2], sf[2 * p + 1][3]));
        }
        __syncwarp();

        // O += P @ V
        unsigned pa[4][4];
        #pragma unroll
        for (int ks = 0; ks < 4; ks++) ldsm_x4(pa[ks], qaddr + ks * 32);
        #pragma unroll
        for (int p = 0; p < 4; p++) {
            unsigned vv[4][4];
            #pragma unroll
            for (int ks = 0; ks < 4; ks++) ldsm_x4(vv[ks], vaddr[p] + ks * 32);
            #pragma unroll
            for (int ks = 0; ks < 4; ks++) {
                mma16(of[2 * p],     pa[ks], vv[ks][0], vv[ks][1]);
                mma16(of[2 * p + 1], pa[ks], vv[ks][2], vv[ks][3]);
            }
        }
        __syncwarp();   // P reads done before next tile's writes
    }

    // Epilogue: normalize, pack fp16 pairs.
    float inv0 = 1.0f / lr[0];
    float inv1 = 1.0f / lr[1];
    #pragma unroll
    for (int nt = 0; nt < 8; nt++) {
        int r0 = q0 + wrow + g;
        int c  = nt * 8 + 2 * q;
        *(unsigned*)&Og[(size_t)r0 * HDIM + c] =
            f2h2(of[nt][0] * inv0, of[nt][1] * inv0);
        *(unsigned*)&Og[(size_t)(r0 + 8) * HDIM + c] =
            f2h2(of[nt][2] * inv1, of[nt][3] * inv1);
    }
}

// ---------------------------------------------------------------------------
// Kernel 3: out = O_perm @ W_proj + b_proj (A gathered fp16 from [b,h,n,d]).
// ---------------------------------------------------------------------------
__global__ __launch_bounds__(256, 2) void proj_gemm_kernel(
    const float* __restrict__ bias,   // [768]
    float* __restrict__ out)          // [8192, 768] fp32
{
    __shared__ unsigned As[128 * 36];
    __shared__ unsigned Bs[128 * 36];

    const int t    = threadIdx.x;
    const int lane = t & 31;
    const int w    = t >> 5;
    const int g    = lane >> 2;
    const int q    = lane & 3;
    const int wm   = (w >> 1) * 32;
    const int wn   = (w & 1) * 64;
    const int m0   = blockIdx.y * 128;
    const int n0   = blockIdx.x * 128;

    const __half* Bsrc = g_WprojTh + (size_t)n0 * EMB;

    unsigned As_u = smem_u32(As), Bs_u = smem_u32(Bs);
    unsigned aaddr[2], baddr[4];
    #pragma unroll
    for (int mt = 0; mt < 2; mt++) aaddr[mt] = addr_a(As_u, wm + mt * 16, lane);
    #pragma unroll
    for (int p = 0; p < 4; p++)    baddr[p]  = addr_b(Bs_u, wn + p * 16, lane);

    float acc[2][8][4] = {};

    for (int kb = 0; kb < EMB / 64; kb++) {
        __syncthreads();
        #pragma unroll
        for (int l = 0; l < 4; l++) {
            int idx = t + l * 256;
            int row = idx >> 3, c8 = idx & 7;
            int m  = m0 + row;
            int bi = m >> 11, ni = m & 2047;
            uint4 ua = *(const uint4*)
                &g_Oh[((size_t)(bi * NHEAD + kb) * SEQ + ni) * HDIM + c8 * 8];
            uint4 ub = *(const uint4*)&Bsrc[(size_t)row * EMB + kb * 64 + c8 * 8];
            *(uint4*)&As[row * 36 + c8 * 4] = ua;
            *(uint4*)&Bs[row * 36 + c8 * 4] = ub;
        }
        __syncthreads();

        #pragma unroll
        for (int ks = 0; ks < 4; ks++) {
            unsigned a0[4], a1[4];
            ldsm_x4(a0, aaddr[0] + ks * 32);
            ldsm_x4(a1, aaddr[1] + ks * 32);
            #pragma unroll
            for (int p = 0; p < 4; p++) {
                unsigned bb[4];
                ldsm_x4(bb, baddr[p] + ks * 32);
                mma16(acc[0][2 * p],     a0, bb[0], bb[1]);
                mma16(acc[0][2 * p + 1], a0, bb[2], bb[3]);
                mma16(acc[1][2 * p],     a1, bb[0], bb[1]);
                mma16(acc[1][2 * p + 1], a1, bb[2], bb[3]);
            }
        }
    }

    #pragma unroll
    for (int mt = 0; mt < 2; mt++) {
        #pragma unroll
        for (int nt = 0; nt < 8; nt++) {
            #pragma unroll
            for (int e = 0; e < 4; e++) {
                int row = m0 + wm + mt * 16 + g + ((e >> 1) ? 8 : 0);
                int col = n0 + wn + nt * 8 + 2 * q + (e & 1);
                out[(size_t)row * EMB + col] = acc[mt][nt][e] + bias[col];
            }
        }
    }
}

// ---------------------------------------------------------------------------
// Launch
// ---------------------------------------------------------------------------
extern "C" void kernel_launch(void* const* d_in, const int* in_sizes, int n_in,
                              void* d_out, int out_size)
{
    const float* x      = (const float*)d_in[0];  // [4,2048,768]
    const float* W_qkv  = (const float*)d_in[1];  // [768,2304]
    const float* b_qkv  = (const float*)d_in[2];  // [2304]
    const float* W_proj = (const float*)d_in[3];  // [768,768]
    const float* b_proj = (const float*)d_in[4];  // [768]
    float* out = (float*)d_out;                   // [4,2048,768]

    // 0) Weight transposes to fp16 K-major [N][K]
    transpose_qkv_kernel<<<dim3(QKV3 / 32, EMB / 32), 256>>>(W_qkv);
    transpose_proj_kernel<<<dim3(EMB / 32, EMB / 32), 256>>>(W_proj);

    // 1) QKV GEMM: M=8192, N=2304
    qkv_gemm_kernel<<<dim3(QKV3 / 128, (BATCH * SEQ) / 128), 256>>>(x, b_qkv);

    // 2) Flash attention: 16 q-tiles x 48 (b,h)
    flash_attn_kernel<<<dim3(SEQ / 128, BHT), 256>>>();

    // 3) Projection GEMM: M=8192, N=768
    proj_gemm_kernel<<<dim3(EMB / 128, (BATCH * SEQ) / 128), 256>>>(b_proj, out);
}

// round 15
// speedup vs baseline: 6.2103x; 1.1242x over previous
#include <cuda_runtime.h>
#include <cuda_fp16.h>
#include <cstdint>

// MultiHeadAttention: b=4, n=2048, emb=768, heads=12, head_dim=64, fp32 in/out.
// Round 13 (resubmit of R12 after broker infra failure): cp.async double-
// buffered tiles in all three main kernels; x pre-converted to fp16.
// fp16 m16n8k16 + ldmatrix/stmatrix + exp2 softmax.

#define EMB    768
#define QKV3   2304
#define NHEAD  12
#define HDIM   64
#define BATCH  4
#define SEQ    2048
#define BHT    (BATCH*NHEAD)
// 1/sqrt(768) * log2(e)
#define ATT_SCALE_LOG2E 0.05206022387508899f

// Scratch (allocation-free rule: __device__ globals). All fp16.
__device__ __half g_Xh[BATCH * SEQ * EMB];   // x converted to fp16
__device__ __half g_Qh[BHT * SEQ * HDIM];
__device__ __half g_Kh[BHT * SEQ * HDIM];
__device__ __half g_Vth[BHT * HDIM * SEQ];   // V transposed: [bh][d][seq]
__device__ __half g_Oh[BHT * SEQ * HDIM];
__device__ __half g_WqkvTh[QKV3 * EMB];      // [N=2304][K=768] fp16
__device__ __half g_WprojTh[EMB * EMB];      // [N=768][K=768] fp16

// ---------------------------------------------------------------------------
// helpers
// ---------------------------------------------------------------------------
__device__ __forceinline__ unsigned f2h2(float lo, float hi) {
    unsigned u;
    asm("cvt.rn.f16x2.f32 %0, %1, %2;" : "=r"(u) : "f"(hi), "f"(lo));
    return u;
}

__device__ __forceinline__ unsigned smem_u32(const void* p) {
    unsigned a;
    asm("{ .reg .u64 t; cvta.to.shared.u64 t, %1; cvt.u32.u64 %0, t; }"
        : "=r"(a) : "l"(p));
    return a;
}

__device__ __forceinline__ void cp16(unsigned saddr, const void* gptr) {
    asm volatile("cp.async.cg.shared.global [%0], [%1], 16;"
                 :: "r"(saddr), "l"(gptr));
}
#define CP_COMMIT() asm volatile("cp.async.commit_group;" ::: "memory")
#define CP_WAIT0()  asm volatile("cp.async.wait_group 0;" ::: "memory")

// D += A * B, m16n8k16 fp16 inputs, fp32 accumulate.
__device__ __forceinline__ void mma16(float d[4], const unsigned a[4],
                                      unsigned b0, unsigned b1) {
    asm volatile(
        "mma.sync.aligned.m16n8k16.row.col.f32.f16.f16.f32 "
        "{%0,%1,%2,%3},{%4,%5,%6,%7},{%8,%9},{%0,%1,%2,%3};"
        : "+f"(d[0]), "+f"(d[1]), "+f"(d[2]), "+f"(d[3])
        : "r"(a[0]), "r"(a[1]), "r"(a[2]), "r"(a[3]), "r"(b0), "r"(b1));
}

__device__ __forceinline__ void ldsm_x4(unsigned r[4], unsigned addr) {
    asm volatile("ldmatrix.sync.aligned.m8n8.x4.shared.b16 {%0,%1,%2,%3}, [%4];"
                 : "=r"(r[0]), "=r"(r[1]), "=r"(r[2]), "=r"(r[3]) : "r"(addr));
}

__device__ __forceinline__ void stsm_x4(unsigned addr, unsigned r0, unsigned r1,
                                        unsigned r2, unsigned r3) {
    asm volatile("stmatrix.sync.aligned.m8n8.x4.shared.b16 [%0], {%1,%2,%3,%4};"
                 :: "r"(addr), "r"(r0), "r"(r1), "r"(r2), "r"(r3) : "memory");
}

// Per-lane address helpers for the stride-36-u32 (144 B) smem layout.
__device__ __forceinline__ unsigned addr_a(unsigned base, int row0, int lane) {
    int l8 = lane & 7, mh = (lane >> 3) & 1, mq = lane >> 4;
    return base + (unsigned)(((row0 + mh * 8 + l8) * 36 + mq * 4) * 4);
}
__device__ __forceinline__ unsigned addr_b(unsigned base, int row0, int lane) {
    int l8 = lane & 7, m = lane >> 3;
    return base + (unsigned)(((row0 + ((m >> 1) & 1) * 8 + l8) * 36 + (m & 1) * 4) * 4);
}

// ---------------------------------------------------------------------------
// Pre-pass kernels
// ---------------------------------------------------------------------------
__global__ __launch_bounds__(256) void convert_x_kernel(const float* __restrict__ x) {
    size_t i = ((size_t)blockIdx.x * 256 + threadIdx.x) * 8;
    float4 a0 = *(const float4*)&x[i];
    float4 a1 = *(const float4*)&x[i + 4];
    uint4 u = { f2h2(a0.x,a0.y), f2h2(a0.z,a0.w), f2h2(a1.x,a1.y), f2h2(a1.z,a1.w) };
    *(uint4*)&g_Xh[i] = u;
}

__global__ __launch_bounds__(256) void transpose_qkv_kernel(const float* __restrict__ W) {
    __shared__ float tile[32][33];
    int tx = threadIdx.x & 31, ty = threadIdx.x >> 5;   // 32 x 8
    int n0 = blockIdx.x * 32, k0 = blockIdx.y * 32;
    #pragma unroll
    for (int j = 0; j < 32; j += 8)
        tile[ty + j][tx] = W[(size_t)(k0 + ty + j) * QKV3 + n0 + tx];
    __syncthreads();
    #pragma unroll
    for (int j = 0; j < 32; j += 8)
        g_WqkvTh[(size_t)(n0 + ty + j) * EMB + k0 + tx] = __float2half(tile[tx][ty + j]);
}

__global__ __launch_bounds__(256) void transpose_proj_kernel(const float* __restrict__ W) {
    __shared__ float tile[32][33];
    int tx = threadIdx.x & 31, ty = threadIdx.x >> 5;
    int n0 = blockIdx.x * 32, k0 = blockIdx.y * 32;
    #pragma unroll
    for (int j = 0; j < 32; j += 8)
        tile[ty + j][tx] = W[(size_t)(k0 + ty + j) * EMB + n0 + tx];
    __syncthreads();
    #pragma unroll
    for (int j = 0; j < 32; j += 8)
        g_WprojTh[(size_t)(n0 + ty + j) * EMB + k0 + tx] = __float2half(tile[tx][ty + j]);
}

// ---------------------------------------------------------------------------
// GEMM smem layout (u32 units, dynamic): A0=0, A1=4608, B0=9216, B1=13824.
// Total 18432 u32 = 73728 B. Buffer step 4608 u32 = 18432 B.
// ---------------------------------------------------------------------------
#define GEMM_SMEM_BYTES 73728
#define BUFSTEP_B 18432u

// Kernel 1: qkv = Xh @ WqkvT + b -> scatter fp16 to g_Qh/g_Kh/g_Vth.
__global__ __launch_bounds__(256, 2) void qkv_gemm_kernel(
    const float* __restrict__ bias)   // [2304]
{
    extern __shared__ unsigned sh[];
    unsigned* A0 = sh;
    unsigned* B0 = sh + 9216;

    const int t    = threadIdx.x;
    const int lane = t & 31;
    const int w    = t >> 5;
    const int g    = lane >> 2;
    const int q    = lane & 3;
    const int wm   = (w >> 1) * 32;
    const int wn   = (w & 1) * 64;
    const int m0   = blockIdx.y * 128;
    const int n0   = blockIdx.x * 128;

    const __half* Asrc = g_Xh + (size_t)m0 * EMB;
    const __half* Bsrc = g_WqkvTh + (size_t)n0 * EMB;

    unsigned A0_u = smem_u32(A0), B0_u = smem_u32(B0);
    unsigned aaddr[2], baddr[4];
    #pragma unroll
    for (int mt = 0; mt < 2; mt++) aaddr[mt] = addr_a(A0_u, wm + mt * 16, lane);
    #pragma unroll
    for (int p = 0; p < 4; p++)    baddr[p]  = addr_b(B0_u, wn + p * 16, lane);

    // Per-thread load slots: 4 chunks, row = idx>>3, c8 = idx&7.
    int rowc[4], c8c[4];
    #pragma unroll
    for (int l = 0; l < 4; l++) {
        int idx = t + l * 256;
        rowc[l] = idx >> 3; c8c[l] = idx & 7;
    }

    // Prologue: tile kb=0 -> buf0.
    #pragma unroll
    for (int l = 0; l < 4; l++) {
        unsigned doff = (unsigned)((rowc[l] * 36 + c8c[l] * 4) * 4);
        cp16(A0_u + doff, Asrc + (size_t)rowc[l] * EMB + c8c[l] * 8);
        cp16(B0_u + doff, Bsrc + (size_t)rowc[l] * EMB + c8c[l] * 8);
    }
    CP_COMMIT(); CP_WAIT0();
    __syncthreads();

    float acc[2][8][4] = {};

    for (int kb = 0; kb < EMB / 64; kb++) {
        const unsigned cur = (kb & 1) * BUFSTEP_B;
        if (kb + 1 < EMB / 64) {
            const unsigned nxt = ((kb + 1) & 1) * BUFSTEP_B;
            const int koff = (kb + 1) * 64;
            #pragma unroll
            for (int l = 0; l < 4; l++) {
                unsigned doff = (unsigned)((rowc[l] * 36 + c8c[l] * 4) * 4);
                cp16(A0_u + nxt + doff, Asrc + (size_t)rowc[l] * EMB + koff + c8c[l] * 8);
                cp16(B0_u + nxt + doff, Bsrc + (size_t)rowc[l] * EMB + koff + c8c[l] * 8);
            }
            CP_COMMIT();
        }

        #pragma unroll
        for (int ks = 0; ks < 4; ks++) {
            unsigned a0[4], a1[4];
            ldsm_x4(a0, aaddr[0] + cur + ks * 32);
            ldsm_x4(a1, aaddr[1] + cur + ks * 32);
            #pragma unroll
            for (int p = 0; p < 4; p++) {
                unsigned bb[4];
                ldsm_x4(bb, baddr[p] + cur + ks * 32);
                mma16(acc[0][2 * p],     a0, bb[0], bb[1]);
                mma16(acc[0][2 * p + 1], a0, bb[2], bb[3]);
                mma16(acc[1][2 * p],     a1, bb[0], bb[1]);
                mma16(acc[1][2 * p + 1], a1, bb[2], bb[3]);
            }
        }
        CP_WAIT0();
        __syncthreads();
    }

    // Scatter: column j -> h=j/192, d=(j%192)/3, s=j%3 (qkv innermost).
    #pragma unroll
    for (int mt = 0; mt < 2; mt++) {
        #pragma unroll
        for (int nt = 0; nt < 8; nt++) {
            #pragma unroll
            for (int e = 0; e < 4; e++) {
                int row = m0 + wm + mt * 16 + g + ((e >> 1) ? 8 : 0);
                int col = n0 + wn + nt * 8 + 2 * q + (e & 1);
                float v = acc[mt][nt][e] + bias[col];
                int bi = row >> 11, ni = row & 2047;
                int h = col / 192;
                int rem = col - h * 192;
                int d = rem / 3;
                int s = rem - d * 3;
                __half hv = __float2half(v);
                if (s == 0)
                    g_Qh[((size_t)(bi * NHEAD + h) * SEQ + ni) * HDIM + d] = hv;
                else if (s == 1)
                    g_Kh[((size_t)(bi * NHEAD + h) * SEQ + ni) * HDIM + d] = hv;
                else
                    g_Vth[((size_t)(bi * NHEAD + h) * HDIM + d) * SEQ + ni] = hv;
            }
        }
    }
}

// ---------------------------------------------------------------------------
// Kernel 2: flash attention, cp.async double-buffered K/V.
// Dynamic smem (u32): Qs=0 (4608), K0=4608, K1=6912, V0=9216, V1=11520.
// Total 13824 u32 = 55296 B. K/V buffer step 2304 u32 = 9216 B.
// ---------------------------------------------------------------------------
#define FLASH_SMEM_BYTES 55296
#define KVSTEP_B 9216u

__global__ __launch_bounds__(256, 2) void flash_attn_kernel()
{
    extern __shared__ unsigned sh[];
    unsigned* Qs = sh;                  // Q staged, then per-warp P

    const int t    = threadIdx.x;
    const int lane = t & 31;
    const int w    = t >> 5;
    const int g    = lane >> 2;
    const int q    = lane & 3;
    const int wrow = w * 16;
    const int bh   = blockIdx.y;
    const int q0   = blockIdx.x * 128;

    const __half* Qg  = g_Qh  + (size_t)bh * SEQ * HDIM;
    const __half* Kg  = g_Kh  + (size_t)bh * SEQ * HDIM;
    const __half* Vtg = g_Vth + (size_t)bh * HDIM * SEQ;
    __half*       Og  = g_Oh  + (size_t)bh * SEQ * HDIM;

    unsigned Qs_u = smem_u32(sh);
    unsigned K0_u = Qs_u + 4608u * 4u;
    unsigned V0_u = Qs_u + 9216u * 4u;

    const unsigned qaddr = addr_a(Qs_u, wrow, lane);   // also P A-frags
    unsigned kaddr[4], vaddr[4], paddr[4];
    #pragma unroll
    for (int p = 0; p < 4; p++) {
        kaddr[p] = addr_b(K0_u, p * 16, lane);
        vaddr[p] = addr_b(V0_u, p * 16, lane);
        int l8 = lane & 7, m = lane >> 3;
        paddr[p] = Qs_u + (unsigned)(((wrow + (m & 1) * 8 + l8) * 36
                                      + (m >> 1) * 4 + p * 8) * 4);
    }

    // Per-thread K/V load slots (2 chunks each).
    int rowc[2], c8c[2];
    #pragma unroll
    for (int l = 0; l < 2; l++) {
        int idx = t + l * 256;
        rowc[l] = idx >> 3; c8c[l] = idx & 7;
    }

    // Stage Q tile (direct uint4 copies) + prologue K/V tile 0 via cp.async.
    #pragma unroll
    for (int l = 0; l < 2; l++) {
        unsigned doff = (unsigned)((rowc[l] * 36 + c8c[l] * 4) * 4);
        cp16(K0_u + doff, Kg  + (size_t)rowc[l] * HDIM + c8c[l] * 8);
        cp16(V0_u + doff, Vtg + (size_t)rowc[l] * SEQ  + c8c[l] * 8);
    }
    CP_COMMIT();
    #pragma unroll
    for (int l = 0; l < 4; l++) {
        int idx = t + l * 256;
        int row = idx >> 3, c8 = idx & 7;
        uint4 u = *(const uint4*)&Qg[(size_t)(q0 + row) * HDIM + c8 * 8];
        *(uint4*)&Qs[row * 36 + c8 * 4] = u;
    }
    CP_WAIT0();
    __syncthreads();

    // Persistent Q A-fragments.
    unsigned qf[4][4];
    #pragma unroll
    for (int ks = 0; ks < 4; ks++) ldsm_x4(qf[ks], qaddr + ks * 32);

    float of[8][4] = {};
    float mr[2] = {-1e30f, -1e30f};
    float lr[2] = {0.f, 0.f};

    const int NT = SEQ / 64;
    for (int kt = 0; kt < NT; kt++) {
        const unsigned cur = (kt & 1) * KVSTEP_B;

        // Issue next tile's loads; they land during mma+softmax below.
        if (kt + 1 < NT) {
            const unsigned nxt = ((kt + 1) & 1) * KVSTEP_B;
            const int k0n = (kt + 1) * 64;
            #pragma unroll
            for (int l = 0; l < 2; l++) {
                unsigned doff = (unsigned)((rowc[l] * 36 + c8c[l] * 4) * 4);
                cp16(K0_u + nxt + doff, Kg  + (size_t)(k0n + rowc[l]) * HDIM + c8c[l] * 8);
                cp16(V0_u + nxt + doff, Vtg + (size_t)rowc[l] * SEQ + k0n + c8c[l] * 8);
            }
            CP_COMMIT();
        }

        // S = Q @ K^T
        float sf[8][4] = {};
        #pragma unroll
        for (int p = 0; p < 4; p++) {
            unsigned bb[4][4];
            #pragma unroll
            for (int ks = 0; ks < 4; ks++) ldsm_x4(bb[ks], kaddr[p] + cur + ks * 32);
            #pragma unroll
            for (int ks = 0; ks < 4; ks++) {
                mma16(sf[2 * p],     qf[ks], bb[ks][0], bb[ks][1]);
                mma16(sf[2 * p + 1], qf[ks], bb[ks][2], bb[ks][3]);
            }
        }
        #pragma unroll
        for (int nt = 0; nt < 8; nt++)
            #pragma unroll
            for (int e = 0; e < 4; e++)
                sf[nt][e] *= ATT_SCALE_LOG2E;   // log2 domain

        // Online softmax (exp2 domain) per row half.
        #pragma unroll
        for (int hh = 0; hh < 2; hh++) {
            float rm = -1e30f;
            #pragma unroll
            for (int nt = 0; nt < 8; nt++)
                rm = fmaxf(rm, fmaxf(sf[nt][2 * hh], sf[nt][2 * hh + 1]));
            rm = fmaxf(rm, __shfl_xor_sync(0xffffffffu, rm, 1));
            rm = fmaxf(rm, __shfl_xor_sync(0xffffffffu, rm, 2));
            float mnew = fmaxf(mr[hh], rm);
            float corr = exp2f(mr[hh] - mnew);
            mr[hh] = mnew;
            float rs = 0.f;
            #pragma unroll
            for (int nt = 0; nt < 8; nt++) {
                float p0 = exp2f(sf[nt][2 * hh] - mnew);
                float p1 = exp2f(sf[nt][2 * hh + 1] - mnew);
                sf[nt][2 * hh] = p0;
                sf[nt][2 * hh + 1] = p1;
                rs += p0 + p1;
            }
            rs += __shfl_xor_sync(0xffffffffu, rs, 1);
            rs += __shfl_xor_sync(0xffffffffu, rs, 2);
            lr[hh] = lr[hh] * corr + rs;
            #pragma unroll
            for (int nt = 0; nt < 8; nt++) {
                of[nt][2 * hh] *= corr;
                of[nt][2 * hh + 1] *= corr;
            }
        }

        // P -> smem via stmatrix.
        #pragma unroll
        for (int p = 0; p < 4; p++) {
            stsm_x4(paddr[p],
                    f2h2(sf[2 * p][0],     sf[2 * p][1]),
                    f2h2(sf[2 * p][2],     sf[2 * p][3]),
                    f2h2(sf[2 * p + 1][0], sf[2 * p + 1][1]),
                    f2h2(sf[2 * p + 1][2], sf[2 * p + 1][3]));
        }
        __syncwarp();

        // O += P @ V
        unsigned pa[4][4];
        #pragma unroll
        for (int ks = 0; ks < 4; ks++) ldsm_x4(pa[ks], qaddr + ks * 32);
        #pragma unroll
        for (int p = 0; p < 4; p++) {
            unsigned vv[4][4];
            #pragma unroll
            for (int ks = 0; ks < 4; ks++) ldsm_x4(vv[ks], vaddr[p] + cur + ks * 32);
            #pragma unroll
            for (int ks = 0; ks < 4; ks++) {
                mma16(of[2 * p],     pa[ks], vv[ks][0], vv[ks][1]);
                mma16(of[2 * p + 1], pa[ks], vv[ks][2], vv[ks][3]);
            }
        }

        CP_WAIT0();        // next tile's data landed
        __syncthreads();   // visible to all warps; P reads also done
    }

    // Epilogue: normalize, pack fp16 pairs.
    float inv0 = 1.0f / lr[0];
    float inv1 = 1.0f / lr[1];
    #pragma unroll
    for (int nt = 0; nt < 8; nt++) {
        int r0 = q0 + wrow + g;
        int c  = nt * 8 + 2 * q;
        *(unsigned*)&Og[(size_t)r0 * HDIM + c] =
            f2h2(of[nt][0] * inv0, of[nt][1] * inv0);
        *(unsigned*)&Og[(size_t)(r0 + 8) * HDIM + c] =
            f2h2(of[nt][2] * inv1, of[nt][3] * inv1);
    }
}

// ---------------------------------------------------------------------------
// Kernel 3: out = O_perm @ W_proj + b_proj (A gathered fp16 from [b,h,n,d]).
// ---------------------------------------------------------------------------
__global__ __launch_bounds__(256, 2) void proj_gemm_kernel(
    const float* __restrict__ bias,   // [768]
    float* __restrict__ out)          // [8192, 768] fp32
{
    extern __shared__ unsigned sh[];
    unsigned* A0 = sh;
    unsigned* B0 = sh + 9216;

    const int t    = threadIdx.x;
    const int lane = t & 31;
    const int w    = t >> 5;
    const int g    = lane >> 2;
    const int q    = lane & 3;
    const int wm   = (w >> 1) * 32;
    const int wn   = (w & 1) * 64;
    const int m0   = blockIdx.y * 128;
    const int n0   = blockIdx.x * 128;

    const __half* Bsrc = g_WprojTh + (size_t)n0 * EMB;

    unsigned A0_u = smem_u32(A0), B0_u = smem_u32(B0);
    unsigned aaddr[2], baddr[4];
    #pragma unroll
    for (int mt = 0; mt < 2; mt++) aaddr[mt] = addr_a(A0_u, wm + mt * 16, lane);
    #pragma unroll
    for (int p = 0; p < 4; p++)    baddr[p]  = addr_b(B0_u, wn + p * 16, lane);

    int rowc[4], c8c[4], bic[4], nic[4];
    #pragma unroll
    for (int l = 0; l < 4; l++) {
        int idx = t + l * 256;
        rowc[l] = idx >> 3; c8c[l] = idx & 7;
        int m = m0 + rowc[l];
        bic[l] = m >> 11; nic[l] = m & 2047;
    }

    // Prologue: kb=0 -> buf0 (head h = 0).
    #pragma unroll
    for (int l = 0; l < 4; l++) {
        unsigned doff = (unsigned)((rowc[l] * 36 + c8c[l] * 4) * 4);
        cp16(A0_u + doff,
             &g_Oh[((size_t)(bic[l] * NHEAD + 0) * SEQ + nic[l]) * HDIM + c8c[l] * 8]);
        cp16(B0_u + doff, Bsrc + (size_t)rowc[l] * EMB + c8c[l] * 8);
    }
    CP_COMMIT(); CP_WAIT0();
    __syncthreads();

    float acc[2][8][4] = {};

    for (int kb = 0; kb < EMB / 64; kb++) {
        const unsigned cur = (kb & 1) * BUFSTEP_B;
        if (kb + 1 < EMB / 64) {
            const unsigned nxt = ((kb + 1) & 1) * BUFSTEP_B;
            const int hn = kb + 1;                 // K-chunk == head
            const int koff = hn * 64;
            #pragma unroll
            for (int l = 0; l < 4; l++) {
                unsigned doff = (unsigned)((rowc[l] * 36 + c8c[l] * 4) * 4);
                cp16(A0_u + nxt + doff,
                     &g_Oh[((size_t)(bic[l] * NHEAD + hn) * SEQ + nic[l]) * HDIM + c8c[l] * 8]);
                cp16(B0_u + nxt + doff, Bsrc + (size_t)rowc[l] * EMB + koff + c8c[l] * 8);
            }
            CP_COMMIT();
        }

        #pragma unroll
        for (int ks = 0; ks < 4; ks++) {
            unsigned a0[4], a1[4];
            ldsm_x4(a0, aaddr[0] + cur + ks * 32);
            ldsm_x4(a1, aaddr[1] + cur + ks * 32);
            #pragma unroll
            for (int p = 0; p < 4; p++) {
                unsigned bb[4];
                ldsm_x4(bb, baddr[p] + cur + ks * 32);
                mma16(acc[0][2 * p],     a0, bb[0], bb[1]);
                mma16(acc[0][2 * p + 1], a0, bb[2], bb[3]);
                mma16(acc[1][2 * p],     a1, bb[0], bb[1]);
                mma16(acc[1][2 * p + 1], a1, bb[2], bb[3]);
            }
        }
        CP_WAIT0();
        __syncthreads();
    }

    #pragma unroll
    for (int mt = 0; mt < 2; mt++) {
        #pragma unroll
        for (int nt = 0; nt < 8; nt++) {
            #pragma unroll
            for (int e = 0; e < 4; e++) {
                int row = m0 + wm + mt * 16 + g + ((e >> 1) ? 8 : 0);
                int col = n0 + wn + nt * 8 + 2 * q + (e & 1);
                out[(size_t)row * EMB + col] = acc[mt][nt][e] + bias[col];
            }
        }
    }
}

// ---------------------------------------------------------------------------
// Launch
// ---------------------------------------------------------------------------
extern "C" void kernel_launch(void* const* d_in, const int* in_sizes, int n_in,
                              void* d_out, int out_size)
{
    const float* x      = (const float*)d_in[0];  // [4,2048,768]
    const float* W_qkv  = (const float*)d_in[1];  // [768,2304]
    const float* b_qkv  = (const float*)d_in[2];  // [2304]
    const float* W_proj = (const float*)d_in[3];  // [768,768]
    const float* b_proj = (const float*)d_in[4];  // [768]
    float* out = (float*)d_out;                   // [4,2048,768]

    static bool attr_set = false;
    if (!attr_set) {
        cudaFuncSetAttribute(qkv_gemm_kernel,
                             cudaFuncAttributeMaxDynamicSharedMemorySize, GEMM_SMEM_BYTES);
        cudaFuncSetAttribute(flash_attn_kernel,
                             cudaFuncAttributeMaxDynamicSharedMemorySize, FLASH_SMEM_BYTES);
        cudaFuncSetAttribute(proj_gemm_kernel,
                             cudaFuncAttributeMaxDynamicSharedMemorySize, GEMM_SMEM_BYTES);
        attr_set = true;
    }

    // 0) Pre-passes: x -> fp16; weights -> fp16 K-major [N][K]
    convert_x_kernel<<<(BATCH * SEQ * EMB) / (256 * 8), 256>>>(x);
    transpose_qkv_kernel<<<dim3(QKV3 / 32, EMB / 32), 256>>>(W_qkv);
    transpose_proj_kernel<<<dim3(EMB / 32, EMB / 32), 256>>>(W_proj);

    // 1) QKV GEMM: M=8192, N=2304
    qkv_gemm_kernel<<<dim3(QKV3 / 128, (BATCH * SEQ) / 128), 256,
                      GEMM_SMEM_BYTES>>>(b_qkv);

    // 2) Flash attention: 16 q-tiles x 48 (b,h)
    flash_attn_kernel<<<dim3(SEQ / 128, BHT), 256, FLASH_SMEM_BYTES>>>();

    // 3) Projection GEMM: M=8192, N=768
    proj_gemm_kernel<<<dim3(EMB / 128, (BATCH * SEQ) / 128), 256,
                       GEMM_SMEM_BYTES>>>(b_proj, out);
}